// round 11
// baseline (speedup 1.0000x reference)
#include <cuda_runtime.h>
#include <cuda_bf16.h>
#include <cuda_fp16.h>
#include <math.h>

#define BB 64
#define TT 512
#define EE 512
#define HH 1024
#define GG 4096   // 4*H
#define CC 4
#define NBLK 64   // persistent recurrence blocks (16 units each)

// ---------------------------------------------------------------------------
// Global scratch (static device arrays — no runtime allocation)
// ---------------------------------------------------------------------------
__device__ float g_xp[(size_t)TT * BB * GG];          // [T][B][4H] input projections
__device__ float g_h[BB * HH];                        // final hidden state
// h staged as fp16 MMA A-fragments: [buf][ktile 64][mtile 4][lane 32] x 16B
__device__ uint4 g_hstage[2][64 * 4 * 32];
__device__ unsigned g_bar;                            // global barrier counter

// xproj operands pre-converted to MMA fragment layout (bf16 hi/lo)
__device__ uint4 g_afrag[(size_t)2048 * 32 * 2 * 32];   // 64 MB
__device__ uint4 g_bfrag[(size_t)32 * 256 * 2 * 32];    // 8 MB

// ---------------------------------------------------------------------------
// helpers
// ---------------------------------------------------------------------------
__device__ __forceinline__ void cpasync16(unsigned dst, const void* src) {
    asm volatile("cp.async.cg.shared.global [%0], [%1], 16;" :: "r"(dst), "l"(src));
}
__device__ __forceinline__ uint4 lds128(unsigned addr) {
    uint4 v;
    asm volatile("ld.shared.v4.u32 {%0,%1,%2,%3}, [%4];"
                 : "=r"(v.x), "=r"(v.y), "=r"(v.z), "=r"(v.w) : "r"(addr));
    return v;
}
__device__ __forceinline__ void mma16816(float* d, const uint4& a, unsigned b0, unsigned b1) {
    asm volatile("mma.sync.aligned.m16n8k16.row.col.f32.bf16.bf16.f32 "
                 "{%0,%1,%2,%3}, {%4,%5,%6,%7}, {%8,%9}, {%0,%1,%2,%3};"
                 : "+f"(d[0]), "+f"(d[1]), "+f"(d[2]), "+f"(d[3])
                 : "r"(a.x), "r"(a.y), "r"(a.z), "r"(a.w), "r"(b0), "r"(b1));
}
__device__ __forceinline__ void mma16816h(float* d, const uint4& a, unsigned b0, unsigned b1) {
    asm volatile("mma.sync.aligned.m16n8k16.row.col.f32.f16.f16.f32 "
                 "{%0,%1,%2,%3}, {%4,%5,%6,%7}, {%8,%9}, {%0,%1,%2,%3};"
                 : "+f"(d[0]), "+f"(d[1]), "+f"(d[2]), "+f"(d[3])
                 : "r"(a.x), "r"(a.y), "r"(a.z), "r"(a.w), "r"(b0), "r"(b1));
}
__device__ __forceinline__ unsigned pack_hi(float x0, float x1) {
    unsigned h0 = (unsigned)__bfloat16_as_ushort(__float2bfloat16(x0));
    unsigned h1 = (unsigned)__bfloat16_as_ushort(__float2bfloat16(x1));
    return h0 | (h1 << 16);
}
__device__ __forceinline__ unsigned pack_lo(float x0, float x1) {
    float r0 = x0 - __bfloat162float(__float2bfloat16(x0));
    float r1 = x1 - __bfloat162float(__float2bfloat16(x1));
    unsigned h0 = (unsigned)__bfloat16_as_ushort(__float2bfloat16(r0));
    unsigned h1 = (unsigned)__bfloat16_as_ushort(__float2bfloat16(r1));
    return h0 | (h1 << 16);
}

// ---------------------------------------------------------------------------
// init
// ---------------------------------------------------------------------------
__global__ void init_kernel() {
    int i = blockIdx.x * blockDim.x + threadIdx.x;
    if (i == 0) g_bar = 0u;
    if (i < 64 * 4 * 32) g_hstage[0][i] = make_uint4(0u, 0u, 0u, 0u);
}

// ---------------------------------------------------------------------------
// conv_a: gather emb rows, convert to bf16 hi/lo A-fragment layout. (validated)
// ---------------------------------------------------------------------------
__global__ __launch_bounds__(256) void conv_a_kernel(
        const int* __restrict__ tokens, const float* __restrict__ emb) {
    int gw = (blockIdx.x * 256 + threadIdx.x) >> 5;
    int lane = threadIdx.x & 31;
    int mt = gw >> 5;          // 0..2047
    int kt = gw & 31;          // 0..31
    int t_ = mt >> 2;
    int b0_ = ((mt & 3) << 4) + (lane >> 2);
    int b1_ = b0_ + 8;
    const float* er0 = emb + (size_t)tokens[b0_ * TT + t_] * EE + kt * 16;
    const float* er1 = emb + (size_t)tokens[b1_ * TT + t_] * EE + kt * 16;

    unsigned hi[4], lo[4];
#pragma unroll
    for (int r2 = 0; r2 < 4; r2++) {
        const float* er = (r2 & 1) ? er1 : er0;
        int kc0 = ((lane & 3) << 1) + ((r2 >> 1) << 3);
        float x0 = er[kc0], x1 = er[kc0 + 1];
        hi[r2] = pack_hi(x0, x1);
        lo[r2] = pack_lo(x0, x1);
    }
    size_t base = ((size_t)(mt * 32 + kt) * 2) * 32 + lane;
    g_afrag[base]      = make_uint4(hi[0], hi[1], hi[2], hi[3]);
    g_afrag[base + 32] = make_uint4(lo[0], lo[1], lo[2], lo[3]);
}

// ---------------------------------------------------------------------------
// conv_b: Wi -> bf16 hi/lo B-fragment layout. (validated)
// ---------------------------------------------------------------------------
__global__ __launch_bounds__(256) void conv_b_kernel(const float* __restrict__ Wi) {
    int gw = (blockIdx.x * 256 + threadIdx.x) >> 5;
    int lane = threadIdx.x & 31;
    int kt = gw >> 8;          // 0..31
    int nt = gw & 255;         // 0..255

    unsigned hi[4], lo[4];
#pragma unroll
    for (int w = 0; w < 4; w++) {
        int n  = ((w >> 1) << 3) + (lane >> 2);
        int kc0 = ((lane & 3) << 1) + ((w & 1) << 3);
        const float* p = Wi + (size_t)(kt * 16 + kc0) * GG + nt * 16 + n;
        float x0 = p[0], x1 = p[GG];
        hi[w] = pack_hi(x0, x1);
        lo[w] = pack_lo(x0, x1);
    }
    size_t base = ((size_t)(kt * 256 + nt) * 2) * 32 + lane;
    g_bfrag[base]      = make_uint4(hi[0], hi[1], hi[2], hi[3]);
    g_bfrag[base + 32] = make_uint4(lo[0], lo[1], lo[2], lo[3]);
}

// ---------------------------------------------------------------------------
// xgemm: XP = X @ Wi + bias via bf16 split-3 MMA. 128x128 tile. (validated)
// ---------------------------------------------------------------------------
#define XG_ABUF 16384
#define XG_BOFF 32768
#define XG_SMEM 65536

__global__ __launch_bounds__(256) void xgemm_kernel(const float* __restrict__ bias) {
    extern __shared__ char smem[];
    const unsigned smem_u32 = (unsigned)__cvta_generic_to_shared(smem);
    const int tid = threadIdx.x;
    const int warp = tid >> 5, lane = tid & 31;
    const int mq = warp & 1;
    const int nq = warp >> 1;
    const int bx = blockIdx.x, by = blockIdx.y;

    const bool isA = tid < 128;
    const int amt = (tid & 127) >> 4;
    const int sub = tid & 15;

    float acc[4][4][4];
#pragma unroll
    for (int i = 0; i < 4; i++)
#pragma unroll
        for (int j = 0; j < 4; j++)
#pragma unroll
            for (int q = 0; q < 4; q++) acc[i][j][q] = 0.f;

#pragma unroll
    for (int j = 0; j < 8; j++) {
        int q = sub * 8 + j;
        int kt = q >> 6, hl = (q >> 5) & 1, ln = q & 31;
        unsigned dst; const uint4* src;
        if (isA) {
            dst = smem_u32 + ((amt * 2 + kt) * 2 + hl) * 512 + ln * 16;
            src = g_afrag + (((size_t)(bx * 8 + amt) * 32 + kt) * 2 + hl) * 32 + ln;
        } else {
            dst = smem_u32 + XG_BOFF + ((kt * 8 + amt) * 2 + hl) * 512 + ln * 16;
            src = g_bfrag + (((size_t)kt * 256 + (by * 8 + amt)) * 2 + hl) * 32 + ln;
        }
        cpasync16(dst, src);
    }
    asm volatile("cp.async.commit_group;");

    for (int c = 0; c < 16; c++) {
        if (c < 15) {
            int buf = (c + 1) & 1;
#pragma unroll
            for (int j = 0; j < 8; j++) {
                int q = sub * 8 + j;
                int kt = q >> 6, hl = (q >> 5) & 1, ln = q & 31;
                int ktg = (c + 1) * 2 + kt;
                unsigned dst; const uint4* src;
                if (isA) {
                    dst = smem_u32 + buf * XG_ABUF + ((amt * 2 + kt) * 2 + hl) * 512 + ln * 16;
                    src = g_afrag + (((size_t)(bx * 8 + amt) * 32 + ktg) * 2 + hl) * 32 + ln;
                } else {
                    dst = smem_u32 + XG_BOFF + buf * XG_ABUF + ((kt * 8 + amt) * 2 + hl) * 512 + ln * 16;
                    src = g_bfrag + (((size_t)ktg * 256 + (by * 8 + amt)) * 2 + hl) * 32 + ln;
                }
                cpasync16(dst, src);
            }
            asm volatile("cp.async.commit_group;");
            asm volatile("cp.async.wait_group 1;");
        } else {
            asm volatile("cp.async.wait_group 0;");
        }
        __syncthreads();

        int buf = c & 1;
#pragma unroll
        for (int kt = 0; kt < 2; kt++) {
            unsigned bb0 = smem_u32 + XG_BOFF + buf * XG_ABUF
                         + ((kt * 8 + nq * 2) * 2) * 512 + (lane << 4);
            uint4 bh0 = lds128(bb0);
            uint4 bl0 = lds128(bb0 + 512);
            uint4 bh1 = lds128(bb0 + 1024);
            uint4 bl1 = lds128(bb0 + 1536);
#pragma unroll
            for (int mi = 0; mi < 4; mi++) {
                unsigned ab = smem_u32 + buf * XG_ABUF
                            + (((mq * 4 + mi) * 2 + kt) * 2) * 512 + (lane << 4);
                uint4 ah = lds128(ab);
                uint4 al = lds128(ab + 512);
                mma16816(acc[mi][0], ah, bh0.x, bh0.y);
                mma16816(acc[mi][0], ah, bl0.x, bl0.y);
                mma16816(acc[mi][0], al, bh0.x, bh0.y);
                mma16816(acc[mi][1], ah, bh0.z, bh0.w);
                mma16816(acc[mi][1], ah, bl0.z, bl0.w);
                mma16816(acc[mi][1], al, bh0.z, bh0.w);
                mma16816(acc[mi][2], ah, bh1.x, bh1.y);
                mma16816(acc[mi][2], ah, bl1.x, bl1.y);
                mma16816(acc[mi][2], al, bh1.x, bh1.y);
                mma16816(acc[mi][3], ah, bh1.z, bh1.w);
                mma16816(acc[mi][3], ah, bl1.z, bl1.w);
                mma16816(acc[mi][3], al, bh1.z, bh1.w);
            }
        }
        __syncthreads();
    }

    const int g = lane >> 2, tq = lane & 3;
#pragma unroll
    for (int mi = 0; mi < 4; mi++) {
        int row = bx * 128 + mq * 64 + mi * 16 + g;
#pragma unroll
        for (int nj = 0; nj < 4; nj++) {
            int col = by * 128 + nq * 32 + nj * 8 + tq * 2;
            float b0 = bias[col], b1 = bias[col + 1];
            float* p0 = g_xp + (size_t)row * GG + col;
            float* p1 = g_xp + (size_t)(row + 8) * GG + col;
            *(float2*)p0 = make_float2(acc[mi][nj][0] + b0, acc[mi][nj][1] + b1);
            *(float2*)p1 = make_float2(acc[mi][nj][2] + b0, acc[mi][nj][3] + b1);
        }
    }
}

// ---------------------------------------------------------------------------
// Persistent recurrence kernel: 64 blocks x 256 threads, 16 units per block.
// Warp w: kq = w & 3 (K-slice, 2 ktiles/chunk), nh = w >> 2 (32-col n-half).
// Two-pass partial accumulation into 2 regions; update sums xp + P0 + P1.
// Smem:
//   [0, 32768)        A double buffer (2 x 16 KB fp16 chunks)
//   [32768, 163840)   Wh B-fragments fp16 [ktile 64][ntile16 4] x 512B
//   [163840, 197120)  2 partial-D regions [64][66] f32 (16896 B each)
//   [197120, 214528)  xp staging [64][68] f32
// ---------------------------------------------------------------------------
#define ABUF_BYTES 16384
#define WOFF 32768
#define POFF 163840
#define PART_STRIDE 66
#define PART_RB (64 * PART_STRIDE * 4)    // 16896
#define XPOFF (POFF + 2 * PART_RB)        // 197632
#define XP_STRIDE 68
#define SMEM_BYTES (XPOFF + 64 * XP_STRIDE * 4)   // 215040

__global__ __launch_bounds__(256, 1) void recurrence_kernel(const float* __restrict__ Wh) {
    extern __shared__ char smem[];
    const int tid  = threadIdx.x;
    const int blk  = blockIdx.x;           // 0..63, owns units 16*blk..16*blk+15
    const int warp = tid >> 5;
    const int kq   = warp & 3;             // K-slice: ktiles kq*2, kq*2+1 per chunk
    const int nh   = warp >> 2;            // n-half: cols nh*32..nh*32+31
    const int lane = tid & 31;
    const unsigned smem_u32 = (unsigned)__cvta_generic_to_shared(smem);

    // one-time: stage Wh slice (64 gate cols) as fp16 B fragments
    for (int idx = tid; idx < 64 * 1024; idx += 256) {
        int k = idx >> 6, n = idx & 63;            // n = type*16 + u
        int gcol = ((n >> 4) << 10) + (blk << 4) + (n & 15);
        float w = Wh[(size_t)k * GG + gcol];
        int kc = k & 15, nl = n & 15;
        int ln = ((nl & 7) << 2) + ((kc & 7) >> 1);
        int by = (((nl >> 3) & 1) << 3) + (((kc >> 3) & 1) << 2) + ((kc & 1) << 1);
        int base = WOFF + ((k >> 4) * 4 + (n >> 4)) * 512 + (ln << 4) + by;
        *(__half*)(smem + base) = __float2half_rn(w);
    }
    __syncthreads();

    const int ub = tid & 63;
    const int up = tid >> 6;       // 0..3; thread handles units up, up+4, up+8, up+12
    float creg[4] = {0.f, 0.f, 0.f, 0.f};

    for (int t = 0; t < TT; t++) {
        const char* hsrc = (const char*)g_hstage[t & 1];

        // prefetch chunk 0 (16 KB) + xp[t] slice (same commit group)
        {
            const char* src = hsrc + tid * 16;
            unsigned dst = smem_u32 + tid * 16;
#pragma unroll
            for (int j = 0; j < 4; j++) cpasync16(dst + j * 4096, src + j * 4096);
            // xp: 1024 16B units; idx = tid*4+e: b=idx>>4, type=(idx>>2)&3, q=idx&3
#pragma unroll
            for (int e = 0; e < 4; e++) {
                int idx = tid * 4 + e;
                int b_ = idx >> 4, type = (idx >> 2) & 3, q = idx & 3;
                const float* s = g_xp + ((size_t)t * BB + b_) * GG
                               + type * HH + (blk << 4) + q * 4;
                unsigned d = smem_u32 + XPOFF
                           + (b_ * XP_STRIDE + type * 16 + q * 4) * 4;
                cpasync16(d, s);
            }
            asm volatile("cp.async.commit_group;");
        }

        float acc[4][4][4];
#pragma unroll
        for (int i = 0; i < 4; i++)
#pragma unroll
            for (int j = 0; j < 4; j++)
#pragma unroll
                for (int q = 0; q < 4; q++) acc[i][j][q] = 0.f;

        for (int c = 0; c < 8; c++) {
            if (c < 7) {
                const char* src = hsrc + (size_t)(c + 1) * ABUF_BYTES + tid * 16;
                unsigned dst = smem_u32 + ((c + 1) & 1) * ABUF_BYTES + tid * 16;
#pragma unroll
                for (int j = 0; j < 4; j++) cpasync16(dst + j * 4096, src + j * 4096);
                asm volatile("cp.async.commit_group;");
                asm volatile("cp.async.wait_group 1;");
            } else {
                asm volatile("cp.async.wait_group 0;");
            }
            __syncthreads();

#pragma unroll
            for (int ki = 0; ki < 2; ki++) {
                int ktl = kq * 2 + ki;                 // ktile within chunk
                int ktg = c * 8 + ktl;                 // global ktile
                unsigned bb = smem_u32 + WOFF + (ktg * 4 + nh * 2) * 512 + (lane << 4);
                uint4 b0 = lds128(bb);
                uint4 b1 = lds128(bb + 512);
#pragma unroll
                for (int mt = 0; mt < 4; mt++) {
                    unsigned ab = smem_u32 + (c & 1) * ABUF_BYTES
                                + (ktl * 4 + mt) * 512 + (lane << 4);
                    uint4 ah = lds128(ab);
                    mma16816h(acc[mt][0], ah, b0.x, b0.y);
                    mma16816h(acc[mt][1], ah, b0.z, b0.w);
                    mma16816h(acc[mt][2], ah, b1.x, b1.y);
                    mma16816h(acc[mt][3], ah, b1.z, b1.w);
                }
            }
            __syncthreads();
        }

        // ---- two-pass partial accumulation into 2 regions ----
        {
            int g = lane >> 2, tq = lane & 3;
            if (kq < 2) {
                float* P = (float*)(smem + POFF + kq * PART_RB);
#pragma unroll
                for (int mt = 0; mt < 4; mt++) {
#pragma unroll
                    for (int nj = 0; nj < 4; nj++) {
                        int row = mt * 16 + g;
                        int col = nh * 32 + nj * 8 + tq * 2;
                        *(float2*)&P[row * PART_STRIDE + col] =
                            make_float2(acc[mt][nj][0], acc[mt][nj][1]);
                        *(float2*)&P[(row + 8) * PART_STRIDE + col] =
                            make_float2(acc[mt][nj][2], acc[mt][nj][3]);
                    }
                }
            }
            __syncthreads();
            if (kq >= 2) {
                float* P = (float*)(smem + POFF + (kq - 2) * PART_RB);
#pragma unroll
                for (int mt = 0; mt < 4; mt++) {
#pragma unroll
                    for (int nj = 0; nj < 4; nj++) {
                        int row = mt * 16 + g;
                        int col = nh * 32 + nj * 8 + tq * 2;
                        float2 v0 = *(float2*)&P[row * PART_STRIDE + col];
                        v0.x += acc[mt][nj][0]; v0.y += acc[mt][nj][1];
                        *(float2*)&P[row * PART_STRIDE + col] = v0;
                        float2 v1 = *(float2*)&P[(row + 8) * PART_STRIDE + col];
                        v1.x += acc[mt][nj][2]; v1.y += acc[mt][nj][3];
                        *(float2*)&P[(row + 8) * PART_STRIDE + col] = v1;
                    }
                }
            }
            __syncthreads();
        }

        // ---- pointwise LSTM update (4 units per thread) ----
        {
            const float* xps = (const float*)(smem + XPOFF);
            const float* P0 = (const float*)(smem + POFF);
            const float* P1 = (const float*)(smem + POFF + PART_RB);
            char* hdst = (char*)g_hstage[(t + 1) & 1];
#pragma unroll
            for (int pi = 0; pi < 4; pi++) {
                int u = up + pi * 4;                 // local unit 0..15
                int unit = (blk << 4) + u;
                float gv[4];
#pragma unroll
                for (int type = 0; type < 4; type++) {
                    int n = type * 16 + u;
                    gv[type] = xps[ub * XP_STRIDE + n]
                             + P0[ub * PART_STRIDE + n]
                             + P1[ub * PART_STRIDE + n];
                }
                float si = 1.f / (1.f + expf(-gv[0]));
                float sf = 1.f / (1.f + expf(-gv[1]));
                float tg = tanhf(gv[2]);
                float so = 1.f / (1.f + expf(-gv[3]));
                float cn = fmaf(sf, creg[pi], si * tg);
                creg[pi] = cn;
                float hn = so * tanhf(cn);

                int r = ub & 15, mt = ub >> 4;
                int kc = unit & 15, ktile = unit >> 4;   // ktile == blk
                int ln  = ((r & 7) << 2) + ((kc & 7) >> 1);
                int reg = (((kc >> 3) & 1) << 1) + ((r >> 3) & 1);
                int off = (ktile * 4 + mt) * 512 + (ln << 4)
                        + (reg << 2) + ((kc & 1) << 1);
                *(__half*)(hdst + off) = __float2half_rn(hn);
                if (t == TT - 1) g_h[ub * HH + unit] = hn;
            }
        }

        // ---- single-counter grid barrier with backoff (validated R7/R10) ----
        __threadfence();
        __syncthreads();
        if (tid == 0) {
            atomicAdd(&g_bar, 1u);
            unsigned tgt = (unsigned)(NBLK * (t + 1));
            while (*((volatile unsigned*)&g_bar) < tgt) __nanosleep(32);
        }
        __syncthreads();
    }
}

// ---------------------------------------------------------------------------
// classifier: 64 blocks (one per batch), 128 threads.
// ---------------------------------------------------------------------------
__global__ __launch_bounds__(128) void classifier_kernel(
        const float* __restrict__ Wd, const float* __restrict__ bd,
        float* __restrict__ out) {
    __shared__ float4 red[4];
    int b = blockIdx.x, tid = threadIdx.x;
    int lane = tid & 31, warp = tid >> 5;
    float4 a = make_float4(0.f, 0.f, 0.f, 0.f);
    for (int k = tid; k < HH; k += 128) {
        float h = g_h[b * HH + k];
        float4 w = *(const float4*)(Wd + k * CC);
        a.x = fmaf(h, w.x, a.x); a.y = fmaf(h, w.y, a.y);
        a.z = fmaf(h, w.z, a.z); a.w = fmaf(h, w.w, a.w);
    }
#pragma unroll
    for (int s = 16; s > 0; s >>= 1) {
        a.x += __shfl_xor_sync(0xffffffffu, a.x, s);
        a.y += __shfl_xor_sync(0xffffffffu, a.y, s);
        a.z += __shfl_xor_sync(0xffffffffu, a.z, s);
        a.w += __shfl_xor_sync(0xffffffffu, a.w, s);
    }
    if (lane == 0) red[warp] = a;
    __syncthreads();
    if (tid == 0) {
        float4 s = red[0];
        s.x += red[1].x + red[2].x + red[3].x;
        s.y += red[1].y + red[2].y + red[3].y;
        s.z += red[1].z + red[2].z + red[3].z;
        s.w += red[1].w + red[2].w + red[3].w;
        out[b * CC + 0] = s.x + bd[0];
        out[b * CC + 1] = s.y + bd[1];
        out[b * CC + 2] = s.z + bd[2];
        out[b * CC + 3] = s.w + bd[3];
    }
}

// ---------------------------------------------------------------------------
// launch: 6 graph nodes
// ---------------------------------------------------------------------------
extern "C" void kernel_launch(void* const* d_in, const int* in_sizes, int n_in,
                              void* d_out, int out_size) {
    const int*   tokens = (const int*)d_in[0];
    const float* emb    = (const float*)d_in[1];
    const float* Wi     = (const float*)d_in[2];
    const float* Wh     = (const float*)d_in[3];
    const float* bias   = (const float*)d_in[4];
    const float* Wd     = (const float*)d_in[5];
    const float* bd     = (const float*)d_in[6];
    float* out = (float*)d_out;

    cudaFuncSetAttribute(recurrence_kernel,
                         cudaFuncAttributeMaxDynamicSharedMemorySize, SMEM_BYTES);
    cudaFuncSetAttribute(xgemm_kernel,
                         cudaFuncAttributeMaxDynamicSharedMemorySize, XG_SMEM);

    init_kernel<<<64, 256>>>();
    conv_a_kernel<<<2048 * 32 / 8, 256>>>(tokens, emb);
    conv_b_kernel<<<32 * 256 / 8, 256>>>(Wi);

    dim3 xg(256, 32);
    xgemm_kernel<<<xg, 256, XG_SMEM>>>(bias);

    recurrence_kernel<<<NBLK, 256, SMEM_BYTES>>>(Wh);

    classifier_kernel<<<BB, 128>>>(Wd, bd, out);
}

// round 12
// speedup vs baseline: 1.2517x; 1.2517x over previous
#include <cuda_runtime.h>
#include <cuda_bf16.h>
#include <cuda_fp16.h>
#include <math.h>

#define BB 64
#define TT 512
#define EE 512
#define HH 1024
#define GG 4096   // 4*H
#define CC 4
#define NBLK 128  // persistent recurrence blocks (8 units each)

// ---------------------------------------------------------------------------
// Global scratch (static device arrays — no runtime allocation)
// ---------------------------------------------------------------------------
__device__ float g_xp[(size_t)TT * BB * GG];          // [T][B][4H] input projections
__device__ float g_h[BB * HH];                        // final hidden state
// h staged as fp16 MMA A-fragments: [buf][ktile 64][mtile 4][lane 32] x 16B
__device__ uint4 g_hstage[2][64 * 4 * 32];
__device__ unsigned g_bar;                            // global barrier counter

// xproj operands pre-converted to MMA fragment layout (bf16 hi/lo)
__device__ uint4 g_afrag[(size_t)2048 * 32 * 2 * 32];   // 64 MB
__device__ uint4 g_bfrag[(size_t)32 * 256 * 2 * 32];    // 8 MB

// ---------------------------------------------------------------------------
// helpers
// ---------------------------------------------------------------------------
__device__ __forceinline__ void cpasync16(unsigned dst, const void* src) {
    asm volatile("cp.async.cg.shared.global [%0], [%1], 16;" :: "r"(dst), "l"(src));
}
__device__ __forceinline__ uint4 lds128(unsigned addr) {
    uint4 v;
    asm volatile("ld.shared.v4.u32 {%0,%1,%2,%3}, [%4];"
                 : "=r"(v.x), "=r"(v.y), "=r"(v.z), "=r"(v.w) : "r"(addr));
    return v;
}
__device__ __forceinline__ void mma16816(float* d, const uint4& a, unsigned b0, unsigned b1) {
    asm volatile("mma.sync.aligned.m16n8k16.row.col.f32.bf16.bf16.f32 "
                 "{%0,%1,%2,%3}, {%4,%5,%6,%7}, {%8,%9}, {%0,%1,%2,%3};"
                 : "+f"(d[0]), "+f"(d[1]), "+f"(d[2]), "+f"(d[3])
                 : "r"(a.x), "r"(a.y), "r"(a.z), "r"(a.w), "r"(b0), "r"(b1));
}
__device__ __forceinline__ void mma16816h(float* d, const uint4& a, unsigned b0, unsigned b1) {
    asm volatile("mma.sync.aligned.m16n8k16.row.col.f32.f16.f16.f32 "
                 "{%0,%1,%2,%3}, {%4,%5,%6,%7}, {%8,%9}, {%0,%1,%2,%3};"
                 : "+f"(d[0]), "+f"(d[1]), "+f"(d[2]), "+f"(d[3])
                 : "r"(a.x), "r"(a.y), "r"(a.z), "r"(a.w), "r"(b0), "r"(b1));
}
__device__ __forceinline__ unsigned pack_hi(float x0, float x1) {
    unsigned h0 = (unsigned)__bfloat16_as_ushort(__float2bfloat16(x0));
    unsigned h1 = (unsigned)__bfloat16_as_ushort(__float2bfloat16(x1));
    return h0 | (h1 << 16);
}
__device__ __forceinline__ unsigned pack_lo(float x0, float x1) {
    float r0 = x0 - __bfloat162float(__float2bfloat16(x0));
    float r1 = x1 - __bfloat162float(__float2bfloat16(x1));
    unsigned h0 = (unsigned)__bfloat16_as_ushort(__float2bfloat16(r0));
    unsigned h1 = (unsigned)__bfloat16_as_ushort(__float2bfloat16(r1));
    return h0 | (h1 << 16);
}

// ---------------------------------------------------------------------------
// init
// ---------------------------------------------------------------------------
__global__ void init_kernel() {
    int i = blockIdx.x * blockDim.x + threadIdx.x;
    if (i == 0) g_bar = 0u;
    if (i < 64 * 4 * 32) g_hstage[0][i] = make_uint4(0u, 0u, 0u, 0u);
}

// ---------------------------------------------------------------------------
// conv_a: gather emb rows, convert to bf16 hi/lo A-fragment layout. (validated)
// ---------------------------------------------------------------------------
__global__ __launch_bounds__(256) void conv_a_kernel(
        const int* __restrict__ tokens, const float* __restrict__ emb) {
    int gw = (blockIdx.x * 256 + threadIdx.x) >> 5;
    int lane = threadIdx.x & 31;
    int mt = gw >> 5;          // 0..2047
    int kt = gw & 31;          // 0..31
    int t_ = mt >> 2;
    int b0_ = ((mt & 3) << 4) + (lane >> 2);
    int b1_ = b0_ + 8;
    const float* er0 = emb + (size_t)tokens[b0_ * TT + t_] * EE + kt * 16;
    const float* er1 = emb + (size_t)tokens[b1_ * TT + t_] * EE + kt * 16;

    unsigned hi[4], lo[4];
#pragma unroll
    for (int r2 = 0; r2 < 4; r2++) {
        const float* er = (r2 & 1) ? er1 : er0;
        int kc0 = ((lane & 3) << 1) + ((r2 >> 1) << 3);
        float x0 = er[kc0], x1 = er[kc0 + 1];
        hi[r2] = pack_hi(x0, x1);
        lo[r2] = pack_lo(x0, x1);
    }
    size_t base = ((size_t)(mt * 32 + kt) * 2) * 32 + lane;
    g_afrag[base]      = make_uint4(hi[0], hi[1], hi[2], hi[3]);
    g_afrag[base + 32] = make_uint4(lo[0], lo[1], lo[2], lo[3]);
}

// ---------------------------------------------------------------------------
// conv_b: Wi -> bf16 hi/lo B-fragment layout. (validated)
// ---------------------------------------------------------------------------
__global__ __launch_bounds__(256) void conv_b_kernel(const float* __restrict__ Wi) {
    int gw = (blockIdx.x * 256 + threadIdx.x) >> 5;
    int lane = threadIdx.x & 31;
    int kt = gw >> 8;          // 0..31
    int nt = gw & 255;         // 0..255

    unsigned hi[4], lo[4];
#pragma unroll
    for (int w = 0; w < 4; w++) {
        int n  = ((w >> 1) << 3) + (lane >> 2);
        int kc0 = ((lane & 3) << 1) + ((w & 1) << 3);
        const float* p = Wi + (size_t)(kt * 16 + kc0) * GG + nt * 16 + n;
        float x0 = p[0], x1 = p[GG];
        hi[w] = pack_hi(x0, x1);
        lo[w] = pack_lo(x0, x1);
    }
    size_t base = ((size_t)(kt * 256 + nt) * 2) * 32 + lane;
    g_bfrag[base]      = make_uint4(hi[0], hi[1], hi[2], hi[3]);
    g_bfrag[base + 32] = make_uint4(lo[0], lo[1], lo[2], lo[3]);
}

// ---------------------------------------------------------------------------
// xgemm: XP = X @ Wi + bias via bf16 split-3 MMA. 128x128 tile. (validated)
// ---------------------------------------------------------------------------
#define XG_ABUF 16384
#define XG_BOFF 32768
#define XG_SMEM 65536

__global__ __launch_bounds__(256) void xgemm_kernel(const float* __restrict__ bias) {
    extern __shared__ char smem[];
    const unsigned smem_u32 = (unsigned)__cvta_generic_to_shared(smem);
    const int tid = threadIdx.x;
    const int warp = tid >> 5, lane = tid & 31;
    const int mq = warp & 1;
    const int nq = warp >> 1;
    const int bx = blockIdx.x, by = blockIdx.y;

    const bool isA = tid < 128;
    const int amt = (tid & 127) >> 4;
    const int sub = tid & 15;

    float acc[4][4][4];
#pragma unroll
    for (int i = 0; i < 4; i++)
#pragma unroll
        for (int j = 0; j < 4; j++)
#pragma unroll
            for (int q = 0; q < 4; q++) acc[i][j][q] = 0.f;

#pragma unroll
    for (int j = 0; j < 8; j++) {
        int q = sub * 8 + j;
        int kt = q >> 6, hl = (q >> 5) & 1, ln = q & 31;
        unsigned dst; const uint4* src;
        if (isA) {
            dst = smem_u32 + ((amt * 2 + kt) * 2 + hl) * 512 + ln * 16;
            src = g_afrag + (((size_t)(bx * 8 + amt) * 32 + kt) * 2 + hl) * 32 + ln;
        } else {
            dst = smem_u32 + XG_BOFF + ((kt * 8 + amt) * 2 + hl) * 512 + ln * 16;
            src = g_bfrag + (((size_t)kt * 256 + (by * 8 + amt)) * 2 + hl) * 32 + ln;
        }
        cpasync16(dst, src);
    }
    asm volatile("cp.async.commit_group;");

    for (int c = 0; c < 16; c++) {
        if (c < 15) {
            int buf = (c + 1) & 1;
#pragma unroll
            for (int j = 0; j < 8; j++) {
                int q = sub * 8 + j;
                int kt = q >> 6, hl = (q >> 5) & 1, ln = q & 31;
                int ktg = (c + 1) * 2 + kt;
                unsigned dst; const uint4* src;
                if (isA) {
                    dst = smem_u32 + buf * XG_ABUF + ((amt * 2 + kt) * 2 + hl) * 512 + ln * 16;
                    src = g_afrag + (((size_t)(bx * 8 + amt) * 32 + ktg) * 2 + hl) * 32 + ln;
                } else {
                    dst = smem_u32 + XG_BOFF + buf * XG_ABUF + ((kt * 8 + amt) * 2 + hl) * 512 + ln * 16;
                    src = g_bfrag + (((size_t)ktg * 256 + (by * 8 + amt)) * 2 + hl) * 32 + ln;
                }
                cpasync16(dst, src);
            }
            asm volatile("cp.async.commit_group;");
            asm volatile("cp.async.wait_group 1;");
        } else {
            asm volatile("cp.async.wait_group 0;");
        }
        __syncthreads();

        int buf = c & 1;
#pragma unroll
        for (int kt = 0; kt < 2; kt++) {
            unsigned bb0 = smem_u32 + XG_BOFF + buf * XG_ABUF
                         + ((kt * 8 + nq * 2) * 2) * 512 + (lane << 4);
            uint4 bh0 = lds128(bb0);
            uint4 bl0 = lds128(bb0 + 512);
            uint4 bh1 = lds128(bb0 + 1024);
            uint4 bl1 = lds128(bb0 + 1536);
#pragma unroll
            for (int mi = 0; mi < 4; mi++) {
                unsigned ab = smem_u32 + buf * XG_ABUF
                            + (((mq * 4 + mi) * 2 + kt) * 2) * 512 + (lane << 4);
                uint4 ah = lds128(ab);
                uint4 al = lds128(ab + 512);
                mma16816(acc[mi][0], ah, bh0.x, bh0.y);
                mma16816(acc[mi][0], ah, bl0.x, bl0.y);
                mma16816(acc[mi][0], al, bh0.x, bh0.y);
                mma16816(acc[mi][1], ah, bh0.z, bh0.w);
                mma16816(acc[mi][1], ah, bl0.z, bl0.w);
                mma16816(acc[mi][1], al, bh0.z, bh0.w);
                mma16816(acc[mi][2], ah, bh1.x, bh1.y);
                mma16816(acc[mi][2], ah, bl1.x, bl1.y);
                mma16816(acc[mi][2], al, bh1.x, bh1.y);
                mma16816(acc[mi][3], ah, bh1.z, bh1.w);
                mma16816(acc[mi][3], ah, bl1.z, bl1.w);
                mma16816(acc[mi][3], al, bh1.z, bh1.w);
            }
        }
        __syncthreads();
    }

    const int g = lane >> 2, tq = lane & 3;
#pragma unroll
    for (int mi = 0; mi < 4; mi++) {
        int row = bx * 128 + mq * 64 + mi * 16 + g;
#pragma unroll
        for (int nj = 0; nj < 4; nj++) {
            int col = by * 128 + nq * 32 + nj * 8 + tq * 2;
            float b0 = bias[col], b1 = bias[col + 1];
            float* p0 = g_xp + (size_t)row * GG + col;
            float* p1 = g_xp + (size_t)(row + 8) * GG + col;
            *(float2*)p0 = make_float2(acc[mi][nj][0] + b0, acc[mi][nj][1] + b1);
            *(float2*)p1 = make_float2(acc[mi][nj][2] + b0, acc[mi][nj][3] + b1);
        }
    }
}

// ---------------------------------------------------------------------------
// Persistent recurrence kernel (R10 structure, 128 blocks, fp16 h x fp16 Wh),
// with ALL 8 chunk copies issued at step start (8 commit groups, 8 regions).
// Warp kh (0..7) computes D[64x32] partial over ktiles ktg = c*8+kh.
// Smem:
//   [0, 131072)         A: 8 chunk regions x 16 KB; [0, 69632) reused for
//                        8 partial-D regions [kh][64][34] f32 after consumption
//   [131072, 196608)    Wh B-fragments (fp16, single plane, 64 KB)
//   [196608, 205824)    xp staging [64][36] f32
// ---------------------------------------------------------------------------
#define ABUF_BYTES 16384
#define PART_STRIDE 34
#define PART_RB (64 * PART_STRIDE * 4)    // 8704 per region
#define WOFF 131072
#define XPOFF 196608
#define XP_STRIDE 36
#define SMEM_BYTES (XPOFF + 64 * XP_STRIDE * 4)   // 205824

__global__ __launch_bounds__(256, 1) void recurrence_kernel(const float* __restrict__ Wh) {
    extern __shared__ char smem[];
    const int tid  = threadIdx.x;
    const int blk  = blockIdx.x;
    const int kh   = tid >> 5;       // warp id = K-slice id
    const int lane = tid & 31;
    const unsigned smem_u32 = (unsigned)__cvta_generic_to_shared(smem);

    // one-time: stage Wh slice as fp16 B fragments (single plane)
    for (int idx = tid; idx < 32 * 1024; idx += 256) {
        int k = idx >> 5, n = idx & 31;
        int gcol = ((n >> 3) << 10) + (blk << 3) + (n & 7);
        float w = Wh[(size_t)k * GG + gcol];
        int kc = k & 15;
        int ln = ((n & 7) << 2) + ((kc & 7) >> 1);
        int by = (((n >> 3) & 1) << 3) + (((kc >> 3) & 1) << 2) + ((kc & 1) << 1);
        int base = WOFF + (((k >> 4) << 1) + (n >> 4)) * 512 + (ln << 4) + by;
        *(__half*)(smem + base) = __float2half_rn(w);
    }
    __syncthreads();

    const int ub = tid & 63;
    const int up = tid >> 6;
    float creg[2] = {0.f, 0.f};

    for (int t = 0; t < TT; t++) {
        const char* hsrc = (const char*)g_hstage[t & 1];

        // issue ALL 8 chunk copies up front (chunk c -> region c, own group);
        // xp[t] slice rides in chunk 0's group.
#pragma unroll
        for (int c = 0; c < 8; c++) {
            const char* src = hsrc + (size_t)c * ABUF_BYTES + tid * 16;
            unsigned dst = smem_u32 + c * ABUF_BYTES + tid * 16;
#pragma unroll
            for (int j = 0; j < 4; j++) cpasync16(dst + j * 4096, src + j * 4096);
            if (c == 0) {
#pragma unroll
                for (int e = 0; e < 2; e++) {
                    int idx = tid * 2 + e;
                    int b_ = idx >> 3, gate = (idx >> 1) & 3, half = idx & 1;
                    const float* s = g_xp + ((size_t)t * BB + b_) * GG
                                   + gate * HH + (blk << 3) + half * 4;
                    unsigned d = smem_u32 + XPOFF
                               + (b_ * XP_STRIDE + gate * 8 + half * 4) * 4;
                    cpasync16(d, s);
                }
            }
            asm volatile("cp.async.commit_group;");
        }

        float acc[4][4][4];
#pragma unroll
        for (int i = 0; i < 4; i++)
#pragma unroll
            for (int j = 0; j < 4; j++)
#pragma unroll
                for (int q = 0; q < 4; q++) acc[i][j][q] = 0.f;

#pragma unroll
        for (int c = 0; c < 8; c++) {
            switch (c) {
                case 0: asm volatile("cp.async.wait_group 7;"); break;
                case 1: asm volatile("cp.async.wait_group 6;"); break;
                case 2: asm volatile("cp.async.wait_group 5;"); break;
                case 3: asm volatile("cp.async.wait_group 4;"); break;
                case 4: asm volatile("cp.async.wait_group 3;"); break;
                case 5: asm volatile("cp.async.wait_group 2;"); break;
                case 6: asm volatile("cp.async.wait_group 1;"); break;
                default: asm volatile("cp.async.wait_group 0;"); break;
            }
            __syncthreads();

            const int ktg = c * 8 + kh;
            unsigned bb0 = smem_u32 + WOFF + (ktg * 2 + 0) * 512 + (lane << 4);
            unsigned bb1 = smem_u32 + WOFF + (ktg * 2 + 1) * 512 + (lane << 4);
            uint4 b0 = lds128(bb0);
            uint4 b1 = lds128(bb1);
#pragma unroll
            for (int mt = 0; mt < 4; mt++) {
                unsigned ab = smem_u32 + c * ABUF_BYTES
                            + (kh * 4 + mt) * 512 + (lane << 4);
                uint4 ah = lds128(ab);
                mma16816h(acc[mt][0], ah, b0.x, b0.y);
                mma16816h(acc[mt][1], ah, b0.z, b0.w);
                mma16816h(acc[mt][2], ah, b1.x, b1.y);
                mma16816h(acc[mt][3], ah, b1.z, b1.w);
            }
        }
        __syncthreads();   // all chunks consumed; A region reusable for partials

        // ---- write per-kh partial D into A region ----
        {
            float* P = (float*)(smem + kh * PART_RB);
            int g = lane >> 2, tq = lane & 3;
#pragma unroll
            for (int mt = 0; mt < 4; mt++) {
#pragma unroll
                for (int nj = 0; nj < 4; nj++) {
                    int row = mt * 16 + g;
                    int col = nj * 8 + tq * 2;
                    *(float2*)&P[row * PART_STRIDE + col] =
                        make_float2(acc[mt][nj][0], acc[mt][nj][1]);
                    *(float2*)&P[(row + 8) * PART_STRIDE + col] =
                        make_float2(acc[mt][nj][2], acc[mt][nj][3]);
                }
            }
        }
        __syncthreads();

        // ---- pointwise LSTM update ----
        {
            const float* xps = (const float*)(smem + XPOFF);
            char* hdst = (char*)g_hstage[(t + 1) & 1];
#pragma unroll
            for (int pi = 0; pi < 2; pi++) {
                int p = up + pi * 4;
                int unit = (blk << 3) + p;
                float gv[4];
#pragma unroll
                for (int type = 0; type < 4; type++) {
                    int n = type * 8 + p;
                    float s = xps[ub * XP_STRIDE + n];
#pragma unroll
                    for (int r = 0; r < 8; r++)
                        s += ((const float*)(smem + r * PART_RB))[ub * PART_STRIDE + n];
                    gv[type] = s;
                }
                float si = 1.f / (1.f + expf(-gv[0]));
                float sf = 1.f / (1.f + expf(-gv[1]));
                float tg = tanhf(gv[2]);
                float so = 1.f / (1.f + expf(-gv[3]));
                float cn = fmaf(sf, creg[pi], si * tg);
                creg[pi] = cn;
                float hn = so * tanhf(cn);

                int r = ub & 15, mt = ub >> 4;
                int kc = unit & 15, ktile = unit >> 4;
                int ln  = ((r & 7) << 2) + ((kc & 7) >> 1);
                int reg = (((kc >> 3) & 1) << 1) + ((r >> 3) & 1);
                int off = (ktile * 4 + mt) * 512 + (ln << 4)
                        + (reg << 2) + ((kc & 1) << 1);
                *(__half*)(hdst + off) = __float2half_rn(hn);
                if (t == TT - 1) g_h[ub * HH + unit] = hn;
            }
        }

        // ---- single-counter grid barrier with backoff (validated R7/R10) ----
        __threadfence();
        __syncthreads();
        if (tid == 0) {
            atomicAdd(&g_bar, 1u);
            unsigned tgt = (unsigned)(NBLK * (t + 1));
            while (*((volatile unsigned*)&g_bar) < tgt) __nanosleep(32);
        }
        __syncthreads();
    }
}

// ---------------------------------------------------------------------------
// classifier: 64 blocks (one per batch), 128 threads.
// ---------------------------------------------------------------------------
__global__ __launch_bounds__(128) void classifier_kernel(
        const float* __restrict__ Wd, const float* __restrict__ bd,
        float* __restrict__ out) {
    __shared__ float4 red[4];
    int b = blockIdx.x, tid = threadIdx.x;
    int lane = tid & 31, warp = tid >> 5;
    float4 a = make_float4(0.f, 0.f, 0.f, 0.f);
    for (int k = tid; k < HH; k += 128) {
        float h = g_h[b * HH + k];
        float4 w = *(const float4*)(Wd + k * CC);
        a.x = fmaf(h, w.x, a.x); a.y = fmaf(h, w.y, a.y);
        a.z = fmaf(h, w.z, a.z); a.w = fmaf(h, w.w, a.w);
    }
#pragma unroll
    for (int s = 16; s > 0; s >>= 1) {
        a.x += __shfl_xor_sync(0xffffffffu, a.x, s);
        a.y += __shfl_xor_sync(0xffffffffu, a.y, s);
        a.z += __shfl_xor_sync(0xffffffffu, a.z, s);
        a.w += __shfl_xor_sync(0xffffffffu, a.w, s);
    }
    if (lane == 0) red[warp] = a;
    __syncthreads();
    if (tid == 0) {
        float4 s = red[0];
        s.x += red[1].x + red[2].x + red[3].x;
        s.y += red[1].y + red[2].y + red[3].y;
        s.z += red[1].z + red[2].z + red[3].z;
        s.w += red[1].w + red[2].w + red[3].w;
        out[b * CC + 0] = s.x + bd[0];
        out[b * CC + 1] = s.y + bd[1];
        out[b * CC + 2] = s.z + bd[2];
        out[b * CC + 3] = s.w + bd[3];
    }
}

// ---------------------------------------------------------------------------
// launch: 6 graph nodes
// ---------------------------------------------------------------------------
extern "C" void kernel_launch(void* const* d_in, const int* in_sizes, int n_in,
                              void* d_out, int out_size) {
    const int*   tokens = (const int*)d_in[0];
    const float* emb    = (const float*)d_in[1];
    const float* Wi     = (const float*)d_in[2];
    const float* Wh     = (const float*)d_in[3];
    const float* bias   = (const float*)d_in[4];
    const float* Wd     = (const float*)d_in[5];
    const float* bd     = (const float*)d_in[6];
    float* out = (float*)d_out;

    cudaFuncSetAttribute(recurrence_kernel,
                         cudaFuncAttributeMaxDynamicSharedMemorySize, SMEM_BYTES);
    cudaFuncSetAttribute(xgemm_kernel,
                         cudaFuncAttributeMaxDynamicSharedMemorySize, XG_SMEM);

    init_kernel<<<64, 256>>>();
    conv_a_kernel<<<2048 * 32 / 8, 256>>>(tokens, emb);
    conv_b_kernel<<<32 * 256 / 8, 256>>>(Wi);

    dim3 xg(256, 32);
    xgemm_kernel<<<xg, 256, XG_SMEM>>>(bias);

    recurrence_kernel<<<NBLK, 256, SMEM_BYTES>>>(Wh);

    classifier_kernel<<<BB, 128>>>(Wd, bd, out);
}

// round 13
// speedup vs baseline: 1.2650x; 1.0106x over previous
#include <cuda_runtime.h>
#include <cuda_bf16.h>
#include <cuda_fp16.h>
#include <math.h>

#define BB 64
#define TT 512
#define EE 512
#define HH 1024
#define GG 4096   // 4*H
#define CC 4
#define NBLK 128  // persistent recurrence blocks (8 units each)

// ---------------------------------------------------------------------------
// Global scratch (static device arrays — no runtime allocation)
// ---------------------------------------------------------------------------
__device__ float g_xp[(size_t)TT * BB * GG];          // [T][B][4H] input projections
__device__ float g_h[BB * HH];                        // final hidden state
// h staged as fp16 MMA A-fragments: [buf][ktile 64][mtile 4][lane 32] x 16B
__device__ uint4 g_hstage[2][64 * 4 * 32];
__device__ unsigned g_bar;                            // global barrier counter

// xproj operands pre-converted to MMA fragment layout (bf16 hi/lo)
__device__ uint4 g_afrag[(size_t)2048 * 32 * 2 * 32];   // 64 MB
__device__ uint4 g_bfrag[(size_t)32 * 256 * 2 * 32];    // 8 MB

// ---------------------------------------------------------------------------
// helpers
// ---------------------------------------------------------------------------
__device__ __forceinline__ void cpasync16(unsigned dst, const void* src) {
    asm volatile("cp.async.cg.shared.global [%0], [%1], 16;" :: "r"(dst), "l"(src));
}
__device__ __forceinline__ uint4 lds128(unsigned addr) {
    uint4 v;
    asm volatile("ld.shared.v4.u32 {%0,%1,%2,%3}, [%4];"
                 : "=r"(v.x), "=r"(v.y), "=r"(v.z), "=r"(v.w) : "r"(addr));
    return v;
}
__device__ __forceinline__ void mma16816(float* d, const uint4& a, unsigned b0, unsigned b1) {
    asm volatile("mma.sync.aligned.m16n8k16.row.col.f32.bf16.bf16.f32 "
                 "{%0,%1,%2,%3}, {%4,%5,%6,%7}, {%8,%9}, {%0,%1,%2,%3};"
                 : "+f"(d[0]), "+f"(d[1]), "+f"(d[2]), "+f"(d[3])
                 : "r"(a.x), "r"(a.y), "r"(a.z), "r"(a.w), "r"(b0), "r"(b1));
}
__device__ __forceinline__ void mma16816h(float* d, const uint4& a, unsigned b0, unsigned b1) {
    asm volatile("mma.sync.aligned.m16n8k16.row.col.f32.f16.f16.f32 "
                 "{%0,%1,%2,%3}, {%4,%5,%6,%7}, {%8,%9}, {%0,%1,%2,%3};"
                 : "+f"(d[0]), "+f"(d[1]), "+f"(d[2]), "+f"(d[3])
                 : "r"(a.x), "r"(a.y), "r"(a.z), "r"(a.w), "r"(b0), "r"(b1));
}
__device__ __forceinline__ unsigned pack_hi(float x0, float x1) {
    unsigned h0 = (unsigned)__bfloat16_as_ushort(__float2bfloat16(x0));
    unsigned h1 = (unsigned)__bfloat16_as_ushort(__float2bfloat16(x1));
    return h0 | (h1 << 16);
}
__device__ __forceinline__ unsigned pack_lo(float x0, float x1) {
    float r0 = x0 - __bfloat162float(__float2bfloat16(x0));
    float r1 = x1 - __bfloat162float(__float2bfloat16(x1));
    unsigned h0 = (unsigned)__bfloat16_as_ushort(__float2bfloat16(r0));
    unsigned h1 = (unsigned)__bfloat16_as_ushort(__float2bfloat16(r1));
    return h0 | (h1 << 16);
}

// ---------------------------------------------------------------------------
// init
// ---------------------------------------------------------------------------
__global__ void init_kernel() {
    int i = blockIdx.x * blockDim.x + threadIdx.x;
    if (i == 0) g_bar = 0u;
    if (i < 64 * 4 * 32) g_hstage[0][i] = make_uint4(0u, 0u, 0u, 0u);
}

// ---------------------------------------------------------------------------
// conv_a: gather emb rows, convert to bf16 hi/lo A-fragment layout. (validated)
// ---------------------------------------------------------------------------
__global__ __launch_bounds__(256) void conv_a_kernel(
        const int* __restrict__ tokens, const float* __restrict__ emb) {
    int gw = (blockIdx.x * 256 + threadIdx.x) >> 5;
    int lane = threadIdx.x & 31;
    int mt = gw >> 5;          // 0..2047
    int kt = gw & 31;          // 0..31
    int t_ = mt >> 2;
    int b0_ = ((mt & 3) << 4) + (lane >> 2);
    int b1_ = b0_ + 8;
    const float* er0 = emb + (size_t)tokens[b0_ * TT + t_] * EE + kt * 16;
    const float* er1 = emb + (size_t)tokens[b1_ * TT + t_] * EE + kt * 16;

    unsigned hi[4], lo[4];
#pragma unroll
    for (int r2 = 0; r2 < 4; r2++) {
        const float* er = (r2 & 1) ? er1 : er0;
        int kc0 = ((lane & 3) << 1) + ((r2 >> 1) << 3);
        float x0 = er[kc0], x1 = er[kc0 + 1];
        hi[r2] = pack_hi(x0, x1);
        lo[r2] = pack_lo(x0, x1);
    }
    size_t base = ((size_t)(mt * 32 + kt) * 2) * 32 + lane;
    g_afrag[base]      = make_uint4(hi[0], hi[1], hi[2], hi[3]);
    g_afrag[base + 32] = make_uint4(lo[0], lo[1], lo[2], lo[3]);
}

// ---------------------------------------------------------------------------
// conv_b: Wi -> bf16 hi/lo B-fragment layout. (validated)
// ---------------------------------------------------------------------------
__global__ __launch_bounds__(256) void conv_b_kernel(const float* __restrict__ Wi) {
    int gw = (blockIdx.x * 256 + threadIdx.x) >> 5;
    int lane = threadIdx.x & 31;
    int kt = gw >> 8;          // 0..31
    int nt = gw & 255;         // 0..255

    unsigned hi[4], lo[4];
#pragma unroll
    for (int w = 0; w < 4; w++) {
        int n  = ((w >> 1) << 3) + (lane >> 2);
        int kc0 = ((lane & 3) << 1) + ((w & 1) << 3);
        const float* p = Wi + (size_t)(kt * 16 + kc0) * GG + nt * 16 + n;
        float x0 = p[0], x1 = p[GG];
        hi[w] = pack_hi(x0, x1);
        lo[w] = pack_lo(x0, x1);
    }
    size_t base = ((size_t)(kt * 256 + nt) * 2) * 32 + lane;
    g_bfrag[base]      = make_uint4(hi[0], hi[1], hi[2], hi[3]);
    g_bfrag[base + 32] = make_uint4(lo[0], lo[1], lo[2], lo[3]);
}

// ---------------------------------------------------------------------------
// xgemm: XP = X @ Wi + bias via bf16 split-3 MMA. 128x128 tile. (validated)
// ---------------------------------------------------------------------------
#define XG_ABUF 16384
#define XG_BOFF 32768
#define XG_SMEM 65536

__global__ __launch_bounds__(256) void xgemm_kernel(const float* __restrict__ bias) {
    extern __shared__ char smem[];
    const unsigned smem_u32 = (unsigned)__cvta_generic_to_shared(smem);
    const int tid = threadIdx.x;
    const int warp = tid >> 5, lane = tid & 31;
    const int mq = warp & 1;
    const int nq = warp >> 1;
    const int bx = blockIdx.x, by = blockIdx.y;

    const bool isA = tid < 128;
    const int amt = (tid & 127) >> 4;
    const int sub = tid & 15;

    float acc[4][4][4];
#pragma unroll
    for (int i = 0; i < 4; i++)
#pragma unroll
        for (int j = 0; j < 4; j++)
#pragma unroll
            for (int q = 0; q < 4; q++) acc[i][j][q] = 0.f;

#pragma unroll
    for (int j = 0; j < 8; j++) {
        int q = sub * 8 + j;
        int kt = q >> 6, hl = (q >> 5) & 1, ln = q & 31;
        unsigned dst; const uint4* src;
        if (isA) {
            dst = smem_u32 + ((amt * 2 + kt) * 2 + hl) * 512 + ln * 16;
            src = g_afrag + (((size_t)(bx * 8 + amt) * 32 + kt) * 2 + hl) * 32 + ln;
        } else {
            dst = smem_u32 + XG_BOFF + ((kt * 8 + amt) * 2 + hl) * 512 + ln * 16;
            src = g_bfrag + (((size_t)kt * 256 + (by * 8 + amt)) * 2 + hl) * 32 + ln;
        }
        cpasync16(dst, src);
    }
    asm volatile("cp.async.commit_group;");

    for (int c = 0; c < 16; c++) {
        if (c < 15) {
            int buf = (c + 1) & 1;
#pragma unroll
            for (int j = 0; j < 8; j++) {
                int q = sub * 8 + j;
                int kt = q >> 6, hl = (q >> 5) & 1, ln = q & 31;
                int ktg = (c + 1) * 2 + kt;
                unsigned dst; const uint4* src;
                if (isA) {
                    dst = smem_u32 + buf * XG_ABUF + ((amt * 2 + kt) * 2 + hl) * 512 + ln * 16;
                    src = g_afrag + (((size_t)(bx * 8 + amt) * 32 + ktg) * 2 + hl) * 32 + ln;
                } else {
                    dst = smem_u32 + XG_BOFF + buf * XG_ABUF + ((kt * 8 + amt) * 2 + hl) * 512 + ln * 16;
                    src = g_bfrag + (((size_t)ktg * 256 + (by * 8 + amt)) * 2 + hl) * 32 + ln;
                }
                cpasync16(dst, src);
            }
            asm volatile("cp.async.commit_group;");
            asm volatile("cp.async.wait_group 1;");
        } else {
            asm volatile("cp.async.wait_group 0;");
        }
        __syncthreads();

        int buf = c & 1;
#pragma unroll
        for (int kt = 0; kt < 2; kt++) {
            unsigned bb0 = smem_u32 + XG_BOFF + buf * XG_ABUF
                         + ((kt * 8 + nq * 2) * 2) * 512 + (lane << 4);
            uint4 bh0 = lds128(bb0);
            uint4 bl0 = lds128(bb0 + 512);
            uint4 bh1 = lds128(bb0 + 1024);
            uint4 bl1 = lds128(bb0 + 1536);
#pragma unroll
            for (int mi = 0; mi < 4; mi++) {
                unsigned ab = smem_u32 + buf * XG_ABUF
                            + (((mq * 4 + mi) * 2 + kt) * 2) * 512 + (lane << 4);
                uint4 ah = lds128(ab);
                uint4 al = lds128(ab + 512);
                mma16816(acc[mi][0], ah, bh0.x, bh0.y);
                mma16816(acc[mi][0], ah, bl0.x, bl0.y);
                mma16816(acc[mi][0], al, bh0.x, bh0.y);
                mma16816(acc[mi][1], ah, bh0.z, bh0.w);
                mma16816(acc[mi][1], ah, bl0.z, bl0.w);
                mma16816(acc[mi][1], al, bh0.z, bh0.w);
                mma16816(acc[mi][2], ah, bh1.x, bh1.y);
                mma16816(acc[mi][2], ah, bl1.x, bl1.y);
                mma16816(acc[mi][2], al, bh1.x, bh1.y);
                mma16816(acc[mi][3], ah, bh1.z, bh1.w);
                mma16816(acc[mi][3], ah, bl1.z, bl1.w);
                mma16816(acc[mi][3], al, bh1.z, bh1.w);
            }
        }
        __syncthreads();
    }

    const int g = lane >> 2, tq = lane & 3;
#pragma unroll
    for (int mi = 0; mi < 4; mi++) {
        int row = bx * 128 + mq * 64 + mi * 16 + g;
#pragma unroll
        for (int nj = 0; nj < 4; nj++) {
            int col = by * 128 + nq * 32 + nj * 8 + tq * 2;
            float b0 = bias[col], b1 = bias[col + 1];
            float* p0 = g_xp + (size_t)row * GG + col;
            float* p1 = g_xp + (size_t)(row + 8) * GG + col;
            *(float2*)p0 = make_float2(acc[mi][nj][0] + b0, acc[mi][nj][1] + b1);
            *(float2*)p1 = make_float2(acc[mi][nj][2] + b0, acc[mi][nj][3] + b1);
        }
    }
}

// ---------------------------------------------------------------------------
// Persistent recurrence kernel (R12 structure) with PER-LANE self-contained
// chunk copies: lane copies exactly the bytes it will lds128, so per-thread
// cp.async.wait_group is sufficient -- NO __syncthreads in the chunk loop.
// Warp kh (0..7) computes D[64x32] partial over ktiles ktg = c*8+kh.
// Smem:
//   [0, 131072)         A: 8 chunk regions x 16 KB; [0, 69632) reused for
//                        8 partial-D regions [kh][64][34] f32 after consumption
//   [131072, 196608)    Wh B-fragments (fp16, single plane, 64 KB)
//   [196608, 205824)    xp staging [64][36] f32
// ---------------------------------------------------------------------------
#define ABUF_BYTES 16384
#define PART_STRIDE 34
#define PART_RB (64 * PART_STRIDE * 4)    // 8704 per region
#define WOFF 131072
#define XPOFF 196608
#define XP_STRIDE 36
#define SMEM_BYTES (XPOFF + 64 * XP_STRIDE * 4)   // 205824

__global__ __launch_bounds__(256, 1) void recurrence_kernel(const float* __restrict__ Wh) {
    extern __shared__ char smem[];
    const int tid  = threadIdx.x;
    const int blk  = blockIdx.x;
    const int kh   = tid >> 5;       // warp id = K-slice id
    const int lane = tid & 31;
    const unsigned smem_u32 = (unsigned)__cvta_generic_to_shared(smem);

    // one-time: stage Wh slice as fp16 B fragments (single plane)
    for (int idx = tid; idx < 32 * 1024; idx += 256) {
        int k = idx >> 5, n = idx & 31;
        int gcol = ((n >> 3) << 10) + (blk << 3) + (n & 7);
        float w = Wh[(size_t)k * GG + gcol];
        int kc = k & 15;
        int ln = ((n & 7) << 2) + ((kc & 7) >> 1);
        int by = (((n >> 3) & 1) << 3) + (((kc >> 3) & 1) << 2) + ((kc & 1) << 1);
        int base = WOFF + (((k >> 4) << 1) + (n >> 4)) * 512 + (ln << 4) + by;
        *(__half*)(smem + base) = __float2half_rn(w);
    }
    __syncthreads();

    const int ub = tid & 63;
    const int up = tid >> 6;
    float creg[2] = {0.f, 0.f};

    for (int t = 0; t < TT; t++) {
        const char* hsrc = (const char*)g_hstage[t & 1];

        // per-lane self-contained copies: lane copies exactly its own MMA
        // read set for chunk c: offsets c*16K + (kh*4+mt)*512 + lane*16.
        // xp[t] slice rides in chunk 0's group.
#pragma unroll
        for (int c = 0; c < 8; c++) {
            unsigned base = (unsigned)(c * ABUF_BYTES + (kh * 4) * 512 + (lane << 4));
#pragma unroll
            for (int mt = 0; mt < 4; mt++)
                cpasync16(smem_u32 + base + mt * 512, hsrc + base + mt * 512);
            if (c == 0) {
#pragma unroll
                for (int e = 0; e < 2; e++) {
                    int idx = tid * 2 + e;
                    int b_ = idx >> 3, gate = (idx >> 1) & 3, half = idx & 1;
                    const float* s = g_xp + ((size_t)t * BB + b_) * GG
                                   + gate * HH + (blk << 3) + half * 4;
                    unsigned d = smem_u32 + XPOFF
                               + (b_ * XP_STRIDE + gate * 8 + half * 4) * 4;
                    cpasync16(d, s);
                }
            }
            asm volatile("cp.async.commit_group;");
        }

        float acc[4][4][4];
#pragma unroll
        for (int i = 0; i < 4; i++)
#pragma unroll
            for (int j = 0; j < 4; j++)
#pragma unroll
                for (int q = 0; q < 4; q++) acc[i][j][q] = 0.f;

        // free-running chunk loop: per-thread wait only, no block syncs
#pragma unroll
        for (int c = 0; c < 8; c++) {
            switch (c) {
                case 0: asm volatile("cp.async.wait_group 7;"); break;
                case 1: asm volatile("cp.async.wait_group 6;"); break;
                case 2: asm volatile("cp.async.wait_group 5;"); break;
                case 3: asm volatile("cp.async.wait_group 4;"); break;
                case 4: asm volatile("cp.async.wait_group 3;"); break;
                case 5: asm volatile("cp.async.wait_group 2;"); break;
                case 6: asm volatile("cp.async.wait_group 1;"); break;
                default: asm volatile("cp.async.wait_group 0;"); break;
            }

            const int ktg = c * 8 + kh;
            unsigned bb0 = smem_u32 + WOFF + (ktg * 2 + 0) * 512 + (lane << 4);
            unsigned bb1 = smem_u32 + WOFF + (ktg * 2 + 1) * 512 + (lane << 4);
            uint4 b0 = lds128(bb0);
            uint4 b1 = lds128(bb1);
#pragma unroll
            for (int mt = 0; mt < 4; mt++) {
                unsigned ab = smem_u32 + c * ABUF_BYTES
                            + (kh * 4 + mt) * 512 + (lane << 4);
                uint4 ah = lds128(ab);
                mma16816h(acc[mt][0], ah, b0.x, b0.y);
                mma16816h(acc[mt][1], ah, b0.z, b0.w);
                mma16816h(acc[mt][2], ah, b1.x, b1.y);
                mma16816h(acc[mt][3], ah, b1.z, b1.w);
            }
        }
        __syncthreads();   // all warps done reading A; regions reusable

        // ---- write per-kh partial D into A region ----
        {
            float* P = (float*)(smem + kh * PART_RB);
            int g = lane >> 2, tq = lane & 3;
#pragma unroll
            for (int mt = 0; mt < 4; mt++) {
#pragma unroll
                for (int nj = 0; nj < 4; nj++) {
                    int row = mt * 16 + g;
                    int col = nj * 8 + tq * 2;
                    *(float2*)&P[row * PART_STRIDE + col] =
                        make_float2(acc[mt][nj][0], acc[mt][nj][1]);
                    *(float2*)&P[(row + 8) * PART_STRIDE + col] =
                        make_float2(acc[mt][nj][2], acc[mt][nj][3]);
                }
            }
        }
        __syncthreads();

        // ---- pointwise LSTM update ----
        {
            const float* xps = (const float*)(smem + XPOFF);
            char* hdst = (char*)g_hstage[(t + 1) & 1];
#pragma unroll
            for (int pi = 0; pi < 2; pi++) {
                int p = up + pi * 4;
                int unit = (blk << 3) + p;
                float gv[4];
#pragma unroll
                for (int type = 0; type < 4; type++) {
                    int n = type * 8 + p;
                    float s = xps[ub * XP_STRIDE + n];
#pragma unroll
                    for (int r = 0; r < 8; r++)
                        s += ((const float*)(smem + r * PART_RB))[ub * PART_STRIDE + n];
                    gv[type] = s;
                }
                float si = 1.f / (1.f + expf(-gv[0]));
                float sf = 1.f / (1.f + expf(-gv[1]));
                float tg = tanhf(gv[2]);
                float so = 1.f / (1.f + expf(-gv[3]));
                float cn = fmaf(sf, creg[pi], si * tg);
                creg[pi] = cn;
                float hn = so * tanhf(cn);

                int r = ub & 15, mt = ub >> 4;
                int kc = unit & 15, ktile = unit >> 4;
                int ln  = ((r & 7) << 2) + ((kc & 7) >> 1);
                int reg = (((kc >> 3) & 1) << 1) + ((r >> 3) & 1);
                int off = (ktile * 4 + mt) * 512 + (ln << 4)
                        + (reg << 2) + ((kc & 1) << 1);
                *(__half*)(hdst + off) = __float2half_rn(hn);
                if (t == TT - 1) g_h[ub * HH + unit] = hn;
            }
        }

        // ---- single-counter grid barrier with backoff (validated) ----
        __threadfence();
        __syncthreads();
        if (tid == 0) {
            atomicAdd(&g_bar, 1u);
            unsigned tgt = (unsigned)(NBLK * (t + 1));
            while (*((volatile unsigned*)&g_bar) < tgt) __nanosleep(32);
        }
        __syncthreads();
    }
}

// ---------------------------------------------------------------------------
// classifier: 64 blocks (one per batch), 128 threads.
// ---------------------------------------------------------------------------
__global__ __launch_bounds__(128) void classifier_kernel(
        const float* __restrict__ Wd, const float* __restrict__ bd,
        float* __restrict__ out) {
    __shared__ float4 red[4];
    int b = blockIdx.x, tid = threadIdx.x;
    int lane = tid & 31, warp = tid >> 5;
    float4 a = make_float4(0.f, 0.f, 0.f, 0.f);
    for (int k = tid; k < HH; k += 128) {
        float h = g_h[b * HH + k];
        float4 w = *(const float4*)(Wd + k * CC);
        a.x = fmaf(h, w.x, a.x); a.y = fmaf(h, w.y, a.y);
        a.z = fmaf(h, w.z, a.z); a.w = fmaf(h, w.w, a.w);
    }
#pragma unroll
    for (int s = 16; s > 0; s >>= 1) {
        a.x += __shfl_xor_sync(0xffffffffu, a.x, s);
        a.y += __shfl_xor_sync(0xffffffffu, a.y, s);
        a.z += __shfl_xor_sync(0xffffffffu, a.z, s);
        a.w += __shfl_xor_sync(0xffffffffu, a.w, s);
    }
    if (lane == 0) red[warp] = a;
    __syncthreads();
    if (tid == 0) {
        float4 s = red[0];
        s.x += red[1].x + red[2].x + red[3].x;
        s.y += red[1].y + red[2].y + red[3].y;
        s.z += red[1].z + red[2].z + red[3].z;
        s.w += red[1].w + red[2].w + red[3].w;
        out[b * CC + 0] = s.x + bd[0];
        out[b * CC + 1] = s.y + bd[1];
        out[b * CC + 2] = s.z + bd[2];
        out[b * CC + 3] = s.w + bd[3];
    }
}

// ---------------------------------------------------------------------------
// launch: 6 graph nodes
// ---------------------------------------------------------------------------
extern "C" void kernel_launch(void* const* d_in, const int* in_sizes, int n_in,
                              void* d_out, int out_size) {
    const int*   tokens = (const int*)d_in[0];
    const float* emb    = (const float*)d_in[1];
    const float* Wi     = (const float*)d_in[2];
    const float* Wh     = (const float*)d_in[3];
    const float* bias   = (const float*)d_in[4];
    const float* Wd     = (const float*)d_in[5];
    const float* bd     = (const float*)d_in[6];
    float* out = (float*)d_out;

    cudaFuncSetAttribute(recurrence_kernel,
                         cudaFuncAttributeMaxDynamicSharedMemorySize, SMEM_BYTES);
    cudaFuncSetAttribute(xgemm_kernel,
                         cudaFuncAttributeMaxDynamicSharedMemorySize, XG_SMEM);

    init_kernel<<<64, 256>>>();
    conv_a_kernel<<<2048 * 32 / 8, 256>>>(tokens, emb);
    conv_b_kernel<<<32 * 256 / 8, 256>>>(Wi);

    dim3 xg(256, 32);
    xgemm_kernel<<<xg, 256, XG_SMEM>>>(bias);

    recurrence_kernel<<<NBLK, 256, SMEM_BYTES>>>(Wh);

    classifier_kernel<<<BB, 128>>>(Wd, bd, out);
}

// round 14
// speedup vs baseline: 1.2859x; 1.0165x over previous
#include <cuda_runtime.h>
#include <cuda_bf16.h>
#include <cuda_fp16.h>
#include <math.h>

#define BB 64
#define TT 512
#define EE 512
#define HH 1024
#define GG 4096   // 4*H
#define CC 4
#define NBLK 128  // persistent recurrence blocks (8 units each)

// ---------------------------------------------------------------------------
// Global scratch (static device arrays — no runtime allocation)
// ---------------------------------------------------------------------------
__device__ float g_xp[(size_t)TT * BB * GG];          // [T][B][4H] input projections
__device__ float g_h[BB * HH];                        // final hidden state
// h staged as fp16 MMA A-fragments: [buf][ktile 64][mtile 4][lane 32] x 16B
__device__ uint4 g_hstage[2][64 * 4 * 32];
__device__ unsigned g_bar;                            // global barrier counter

// xproj operands pre-converted to MMA fragment layout (bf16 hi/lo)
__device__ uint4 g_afrag[(size_t)2048 * 32 * 2 * 32];   // 64 MB
__device__ uint4 g_bfrag[(size_t)32 * 256 * 2 * 32];    // 8 MB

// ---------------------------------------------------------------------------
// helpers
// ---------------------------------------------------------------------------
__device__ __forceinline__ void cpasync16(unsigned dst, const void* src) {
    asm volatile("cp.async.cg.shared.global [%0], [%1], 16;" :: "r"(dst), "l"(src));
}
__device__ __forceinline__ uint4 lds128(unsigned addr) {
    uint4 v;
    asm volatile("ld.shared.v4.u32 {%0,%1,%2,%3}, [%4];"
                 : "=r"(v.x), "=r"(v.y), "=r"(v.z), "=r"(v.w) : "r"(addr));
    return v;
}
__device__ __forceinline__ uint4 ldgcg128(const uint4* p) {
    uint4 v;
    asm volatile("ld.global.cg.v4.u32 {%0,%1,%2,%3}, [%4];"
                 : "=r"(v.x), "=r"(v.y), "=r"(v.z), "=r"(v.w) : "l"(p));
    return v;
}
__device__ __forceinline__ void mma16816(float* d, const uint4& a, unsigned b0, unsigned b1) {
    asm volatile("mma.sync.aligned.m16n8k16.row.col.f32.bf16.bf16.f32 "
                 "{%0,%1,%2,%3}, {%4,%5,%6,%7}, {%8,%9}, {%0,%1,%2,%3};"
                 : "+f"(d[0]), "+f"(d[1]), "+f"(d[2]), "+f"(d[3])
                 : "r"(a.x), "r"(a.y), "r"(a.z), "r"(a.w), "r"(b0), "r"(b1));
}
__device__ __forceinline__ void mma16816h(float* d, const uint4& a, unsigned b0, unsigned b1) {
    asm volatile("mma.sync.aligned.m16n8k16.row.col.f32.f16.f16.f32 "
                 "{%0,%1,%2,%3}, {%4,%5,%6,%7}, {%8,%9}, {%0,%1,%2,%3};"
                 : "+f"(d[0]), "+f"(d[1]), "+f"(d[2]), "+f"(d[3])
                 : "r"(a.x), "r"(a.y), "r"(a.z), "r"(a.w), "r"(b0), "r"(b1));
}
__device__ __forceinline__ unsigned pack_hi(float x0, float x1) {
    unsigned h0 = (unsigned)__bfloat16_as_ushort(__float2bfloat16(x0));
    unsigned h1 = (unsigned)__bfloat16_as_ushort(__float2bfloat16(x1));
    return h0 | (h1 << 16);
}
__device__ __forceinline__ unsigned pack_lo(float x0, float x1) {
    float r0 = x0 - __bfloat162float(__float2bfloat16(x0));
    float r1 = x1 - __bfloat162float(__float2bfloat16(x1));
    unsigned h0 = (unsigned)__bfloat16_as_ushort(__float2bfloat16(r0));
    unsigned h1 = (unsigned)__bfloat16_as_ushort(__float2bfloat16(r1));
    return h0 | (h1 << 16);
}

// ---------------------------------------------------------------------------
// init
// ---------------------------------------------------------------------------
__global__ void init_kernel() {
    int i = blockIdx.x * blockDim.x + threadIdx.x;
    if (i == 0) g_bar = 0u;
    if (i < 64 * 4 * 32) g_hstage[0][i] = make_uint4(0u, 0u, 0u, 0u);
}

// ---------------------------------------------------------------------------
// conv_a: gather emb rows, convert to bf16 hi/lo A-fragment layout. (validated)
// ---------------------------------------------------------------------------
__global__ __launch_bounds__(256) void conv_a_kernel(
        const int* __restrict__ tokens, const float* __restrict__ emb) {
    int gw = (blockIdx.x * 256 + threadIdx.x) >> 5;
    int lane = threadIdx.x & 31;
    int mt = gw >> 5;          // 0..2047
    int kt = gw & 31;          // 0..31
    int t_ = mt >> 2;
    int b0_ = ((mt & 3) << 4) + (lane >> 2);
    int b1_ = b0_ + 8;
    const float* er0 = emb + (size_t)tokens[b0_ * TT + t_] * EE + kt * 16;
    const float* er1 = emb + (size_t)tokens[b1_ * TT + t_] * EE + kt * 16;

    unsigned hi[4], lo[4];
#pragma unroll
    for (int r2 = 0; r2 < 4; r2++) {
        const float* er = (r2 & 1) ? er1 : er0;
        int kc0 = ((lane & 3) << 1) + ((r2 >> 1) << 3);
        float x0 = er[kc0], x1 = er[kc0 + 1];
        hi[r2] = pack_hi(x0, x1);
        lo[r2] = pack_lo(x0, x1);
    }
    size_t base = ((size_t)(mt * 32 + kt) * 2) * 32 + lane;
    g_afrag[base]      = make_uint4(hi[0], hi[1], hi[2], hi[3]);
    g_afrag[base + 32] = make_uint4(lo[0], lo[1], lo[2], lo[3]);
}

// ---------------------------------------------------------------------------
// conv_b: Wi -> bf16 hi/lo B-fragment layout. (validated)
// ---------------------------------------------------------------------------
__global__ __launch_bounds__(256) void conv_b_kernel(const float* __restrict__ Wi) {
    int gw = (blockIdx.x * 256 + threadIdx.x) >> 5;
    int lane = threadIdx.x & 31;
    int kt = gw >> 8;          // 0..31
    int nt = gw & 255;         // 0..255

    unsigned hi[4], lo[4];
#pragma unroll
    for (int w = 0; w < 4; w++) {
        int n  = ((w >> 1) << 3) + (lane >> 2);
        int kc0 = ((lane & 3) << 1) + ((w & 1) << 3);
        const float* p = Wi + (size_t)(kt * 16 + kc0) * GG + nt * 16 + n;
        float x0 = p[0], x1 = p[GG];
        hi[w] = pack_hi(x0, x1);
        lo[w] = pack_lo(x0, x1);
    }
    size_t base = ((size_t)(kt * 256 + nt) * 2) * 32 + lane;
    g_bfrag[base]      = make_uint4(hi[0], hi[1], hi[2], hi[3]);
    g_bfrag[base + 32] = make_uint4(lo[0], lo[1], lo[2], lo[3]);
}

// ---------------------------------------------------------------------------
// xgemm: XP = X @ Wi + bias via bf16 split-3 MMA. 128x128 tile. (validated)
// ---------------------------------------------------------------------------
#define XG_ABUF 16384
#define XG_BOFF 32768
#define XG_SMEM 65536

__global__ __launch_bounds__(256) void xgemm_kernel(const float* __restrict__ bias) {
    extern __shared__ char smem[];
    const unsigned smem_u32 = (unsigned)__cvta_generic_to_shared(smem);
    const int tid = threadIdx.x;
    const int warp = tid >> 5, lane = tid & 31;
    const int mq = warp & 1;
    const int nq = warp >> 1;
    const int bx = blockIdx.x, by = blockIdx.y;

    const bool isA = tid < 128;
    const int amt = (tid & 127) >> 4;
    const int sub = tid & 15;

    float acc[4][4][4];
#pragma unroll
    for (int i = 0; i < 4; i++)
#pragma unroll
        for (int j = 0; j < 4; j++)
#pragma unroll
            for (int q = 0; q < 4; q++) acc[i][j][q] = 0.f;

#pragma unroll
    for (int j = 0; j < 8; j++) {
        int q = sub * 8 + j;
        int kt = q >> 6, hl = (q >> 5) & 1, ln = q & 31;
        unsigned dst; const uint4* src;
        if (isA) {
            dst = smem_u32 + ((amt * 2 + kt) * 2 + hl) * 512 + ln * 16;
            src = g_afrag + (((size_t)(bx * 8 + amt) * 32 + kt) * 2 + hl) * 32 + ln;
        } else {
            dst = smem_u32 + XG_BOFF + ((kt * 8 + amt) * 2 + hl) * 512 + ln * 16;
            src = g_bfrag + (((size_t)kt * 256 + (by * 8 + amt)) * 2 + hl) * 32 + ln;
        }
        cpasync16(dst, src);
    }
    asm volatile("cp.async.commit_group;");

    for (int c = 0; c < 16; c++) {
        if (c < 15) {
            int buf = (c + 1) & 1;
#pragma unroll
            for (int j = 0; j < 8; j++) {
                int q = sub * 8 + j;
                int kt = q >> 6, hl = (q >> 5) & 1, ln = q & 31;
                int ktg = (c + 1) * 2 + kt;
                unsigned dst; const uint4* src;
                if (isA) {
                    dst = smem_u32 + buf * XG_ABUF + ((amt * 2 + kt) * 2 + hl) * 512 + ln * 16;
                    src = g_afrag + (((size_t)(bx * 8 + amt) * 32 + ktg) * 2 + hl) * 32 + ln;
                } else {
                    dst = smem_u32 + XG_BOFF + buf * XG_ABUF + ((kt * 8 + amt) * 2 + hl) * 512 + ln * 16;
                    src = g_bfrag + (((size_t)ktg * 256 + (by * 8 + amt)) * 2 + hl) * 32 + ln;
                }
                cpasync16(dst, src);
            }
            asm volatile("cp.async.commit_group;");
            asm volatile("cp.async.wait_group 1;");
        } else {
            asm volatile("cp.async.wait_group 0;");
        }
        __syncthreads();

        int buf = c & 1;
#pragma unroll
        for (int kt = 0; kt < 2; kt++) {
            unsigned bb0 = smem_u32 + XG_BOFF + buf * XG_ABUF
                         + ((kt * 8 + nq * 2) * 2) * 512 + (lane << 4);
            uint4 bh0 = lds128(bb0);
            uint4 bl0 = lds128(bb0 + 512);
            uint4 bh1 = lds128(bb0 + 1024);
            uint4 bl1 = lds128(bb0 + 1536);
#pragma unroll
            for (int mi = 0; mi < 4; mi++) {
                unsigned ab = smem_u32 + buf * XG_ABUF
                            + (((mq * 4 + mi) * 2 + kt) * 2) * 512 + (lane << 4);
                uint4 ah = lds128(ab);
                uint4 al = lds128(ab + 512);
                mma16816(acc[mi][0], ah, bh0.x, bh0.y);
                mma16816(acc[mi][0], ah, bl0.x, bl0.y);
                mma16816(acc[mi][0], al, bh0.x, bh0.y);
                mma16816(acc[mi][1], ah, bh0.z, bh0.w);
                mma16816(acc[mi][1], ah, bl0.z, bl0.w);
                mma16816(acc[mi][1], al, bh0.z, bh0.w);
                mma16816(acc[mi][2], ah, bh1.x, bh1.y);
                mma16816(acc[mi][2], ah, bl1.x, bl1.y);
                mma16816(acc[mi][2], al, bh1.x, bh1.y);
                mma16816(acc[mi][3], ah, bh1.z, bh1.w);
                mma16816(acc[mi][3], ah, bl1.z, bl1.w);
                mma16816(acc[mi][3], al, bh1.z, bh1.w);
            }
        }
        __syncthreads();
    }

    const int g = lane >> 2, tq = lane & 3;
#pragma unroll
    for (int mi = 0; mi < 4; mi++) {
        int row = bx * 128 + mq * 64 + mi * 16 + g;
#pragma unroll
        for (int nj = 0; nj < 4; nj++) {
            int col = by * 128 + nq * 32 + nj * 8 + tq * 2;
            float b0 = bias[col], b1 = bias[col + 1];
            float* p0 = g_xp + (size_t)row * GG + col;
            float* p1 = g_xp + (size_t)(row + 8) * GG + col;
            *(float2*)p0 = make_float2(acc[mi][nj][0] + b0, acc[mi][nj][1] + b1);
            *(float2*)p1 = make_float2(acc[mi][nj][2] + b0, acc[mi][nj][3] + b1);
        }
    }
}

// ---------------------------------------------------------------------------
// Persistent recurrence kernel: A operand loaded DIRECTLY from global to
// registers via ld.global.cg.v4 (per-lane exact read set; no smem staging,
// no cp.async for h, no chunk syncs). Warp kh owns ktiles c*8+kh.
// Smem:
//   [0, 65536)          Wh B-fragments (fp16, single plane, 64 KB)
//   [65536, 135168)     8 partial-D regions [kh][64][34] f32 (dedicated)
//   [135168, 144384)    xp staging [64][36] f32
// ---------------------------------------------------------------------------
#define ABUF_BYTES 16384
#define PART_STRIDE 34
#define PART_RB (64 * PART_STRIDE * 4)    // 8704 per region
#define WOFF 0
#define POFF 65536
#define XPOFF 135168
#define XP_STRIDE 36
#define SMEM_BYTES (XPOFF + 64 * XP_STRIDE * 4)   // 144384

__global__ __launch_bounds__(256, 1) void recurrence_kernel(const float* __restrict__ Wh) {
    extern __shared__ char smem[];
    const int tid  = threadIdx.x;
    const int blk  = blockIdx.x;
    const int kh   = tid >> 5;       // warp id = K-slice id
    const int lane = tid & 31;
    const unsigned smem_u32 = (unsigned)__cvta_generic_to_shared(smem);

    // one-time: stage Wh slice as fp16 B fragments (single plane)
    for (int idx = tid; idx < 32 * 1024; idx += 256) {
        int k = idx >> 5, n = idx & 31;
        int gcol = ((n >> 3) << 10) + (blk << 3) + (n & 7);
        float w = Wh[(size_t)k * GG + gcol];
        int kc = k & 15;
        int ln = ((n & 7) << 2) + ((kc & 7) >> 1);
        int by = (((n >> 3) & 1) << 3) + (((kc >> 3) & 1) << 2) + ((kc & 1) << 1);
        int base = WOFF + (((k >> 4) << 1) + (n >> 4)) * 512 + (ln << 4) + by;
        *(__half*)(smem + base) = __float2half_rn(w);
    }
    __syncthreads();

    const int ub = tid & 63;
    const int up = tid >> 6;       // 0..3; thread owns adjacent units 2up, 2up+1
    float creg[2] = {0.f, 0.f};

    for (int t = 0; t < TT; t++) {
        const char* hsrc = (const char*)g_hstage[t & 1];

        // xp[t] slice prefetch (only cp.async use; overlaps entire GEMM)
        {
#pragma unroll
            for (int e = 0; e < 2; e++) {
                int idx = tid * 2 + e;
                int b_ = idx >> 3, gate = (idx >> 1) & 3, half = idx & 1;
                const float* s = g_xp + ((size_t)t * BB + b_) * GG
                               + gate * HH + (blk << 3) + half * 4;
                unsigned d = smem_u32 + XPOFF
                           + (b_ * XP_STRIDE + gate * 8 + half * 4) * 4;
                cpasync16(d, s);
            }
            asm volatile("cp.async.commit_group;");
        }

        float acc[4][4][4];
#pragma unroll
        for (int i = 0; i < 4; i++)
#pragma unroll
            for (int j = 0; j < 4; j++)
#pragma unroll
                for (int q = 0; q < 4; q++) acc[i][j][q] = 0.f;

        // free-running GEMM: direct global->register A loads (L2, .cg)
#pragma unroll
        for (int c = 0; c < 8; c++) {
            const int ktg = c * 8 + kh;
            unsigned bb0 = smem_u32 + WOFF + (ktg * 2 + 0) * 512 + (lane << 4);
            unsigned bb1 = smem_u32 + WOFF + (ktg * 2 + 1) * 512 + (lane << 4);
            uint4 b0 = lds128(bb0);
            uint4 b1 = lds128(bb1);
            uint4 ah[4];
#pragma unroll
            for (int mt = 0; mt < 4; mt++) {
                size_t byteoff = (size_t)c * ABUF_BYTES + (kh * 4 + mt) * 512 + (lane << 4);
                ah[mt] = ldgcg128((const uint4*)(hsrc + byteoff));
            }
#pragma unroll
            for (int mt = 0; mt < 4; mt++) {
                mma16816h(acc[mt][0], ah[mt], b0.x, b0.y);
                mma16816h(acc[mt][1], ah[mt], b0.z, b0.w);
                mma16816h(acc[mt][2], ah[mt], b1.x, b1.y);
                mma16816h(acc[mt][3], ah[mt], b1.z, b1.w);
            }
        }

        // ---- write per-kh partial D (dedicated region, no aliasing) ----
        {
            float* P = (float*)(smem + POFF + kh * PART_RB);
            int g = lane >> 2, tq = lane & 3;
#pragma unroll
            for (int mt = 0; mt < 4; mt++) {
#pragma unroll
                for (int nj = 0; nj < 4; nj++) {
                    int row = mt * 16 + g;
                    int col = nj * 8 + tq * 2;
                    *(float2*)&P[row * PART_STRIDE + col] =
                        make_float2(acc[mt][nj][0], acc[mt][nj][1]);
                    *(float2*)&P[(row + 8) * PART_STRIDE + col] =
                        make_float2(acc[mt][nj][2], acc[mt][nj][3]);
                }
            }
        }
        asm volatile("cp.async.wait_group 0;");   // xp ready (per-thread)
        __syncthreads();                          // partials visible block-wide

        // ---- pointwise LSTM update: adjacent units 2up, 2up+1 ----
        {
            const float* xps = (const float*)(smem + XPOFF);
            char* hdst = (char*)g_hstage[(t + 1) & 1];
            float hn[2];
#pragma unroll
            for (int pi = 0; pi < 2; pi++) {
                int p = 2 * up + pi;
                float gv[4];
#pragma unroll
                for (int type = 0; type < 4; type++) {
                    int n = type * 8 + p;
                    float s = xps[ub * XP_STRIDE + n];
#pragma unroll
                    for (int r = 0; r < 8; r++)
                        s += ((const float*)(smem + POFF + r * PART_RB))[ub * PART_STRIDE + n];
                    gv[type] = s;
                }
                float si = 1.f / (1.f + expf(-gv[0]));
                float sf = 1.f / (1.f + expf(-gv[1]));
                float tg = tanhf(gv[2]);
                float so = 1.f / (1.f + expf(-gv[3]));
                float cn = fmaf(sf, creg[pi], si * tg);
                creg[pi] = cn;
                hn[pi] = so * tanhf(cn);
                if (t == TT - 1) g_h[ub * HH + (blk << 3) + p] = hn[pi];
            }

            // packed u32 store: units 2up (lo half) and 2up+1 (hi half)
            {
                int unit0 = (blk << 3) + 2 * up;      // even unit
                int r = ub & 15, mt = ub >> 4;
                int kc = unit0 & 15, ktile = unit0 >> 4;
                int ln  = ((r & 7) << 2) + ((kc & 7) >> 1);
                int reg = (((kc >> 3) & 1) << 1) + ((r >> 3) & 1);
                int off = (ktile * 4 + mt) * 512 + (ln << 4) + (reg << 2);
                unsigned h0 = (unsigned)__half_as_ushort(__float2half_rn(hn[0]));
                unsigned h1 = (unsigned)__half_as_ushort(__float2half_rn(hn[1]));
                *(unsigned*)(hdst + off) = h0 | (h1 << 16);
            }
        }

        // ---- single-counter grid barrier with backoff (validated) ----
        __threadfence();
        __syncthreads();
        if (tid == 0) {
            atomicAdd(&g_bar, 1u);
            unsigned tgt = (unsigned)(NBLK * (t + 1));
            while (*((volatile unsigned*)&g_bar) < tgt) __nanosleep(32);
        }
        __syncthreads();
    }
}

// ---------------------------------------------------------------------------
// classifier: 64 blocks (one per batch), 128 threads.
// ---------------------------------------------------------------------------
__global__ __launch_bounds__(128) void classifier_kernel(
        const float* __restrict__ Wd, const float* __restrict__ bd,
        float* __restrict__ out) {
    __shared__ float4 red[4];
    int b = blockIdx.x, tid = threadIdx.x;
    int lane = tid & 31, warp = tid >> 5;
    float4 a = make_float4(0.f, 0.f, 0.f, 0.f);
    for (int k = tid; k < HH; k += 128) {
        float h = g_h[b * HH + k];
        float4 w = *(const float4*)(Wd + k * CC);
        a.x = fmaf(h, w.x, a.x); a.y = fmaf(h, w.y, a.y);
        a.z = fmaf(h, w.z, a.z); a.w = fmaf(h, w.w, a.w);
    }
#pragma unroll
    for (int s = 16; s > 0; s >>= 1) {
        a.x += __shfl_xor_sync(0xffffffffu, a.x, s);
        a.y += __shfl_xor_sync(0xffffffffu, a.y, s);
        a.z += __shfl_xor_sync(0xffffffffu, a.z, s);
        a.w += __shfl_xor_sync(0xffffffffu, a.w, s);
    }
    if (lane == 0) red[warp] = a;
    __syncthreads();
    if (tid == 0) {
        float4 s = red[0];
        s.x += red[1].x + red[2].x + red[3].x;
        s.y += red[1].y + red[2].y + red[3].y;
        s.z += red[1].z + red[2].z + red[3].z;
        s.w += red[1].w + red[2].w + red[3].w;
        out[b * CC + 0] = s.x + bd[0];
        out[b * CC + 1] = s.y + bd[1];
        out[b * CC + 2] = s.z + bd[2];
        out[b * CC + 3] = s.w + bd[3];
    }
}

// ---------------------------------------------------------------------------
// launch: 6 graph nodes
// ---------------------------------------------------------------------------
extern "C" void kernel_launch(void* const* d_in, const int* in_sizes, int n_in,
                              void* d_out, int out_size) {
    const int*   tokens = (const int*)d_in[0];
    const float* emb    = (const float*)d_in[1];
    const float* Wi     = (const float*)d_in[2];
    const float* Wh     = (const float*)d_in[3];
    const float* bias   = (const float*)d_in[4];
    const float* Wd     = (const float*)d_in[5];
    const float* bd     = (const float*)d_in[6];
    float* out = (float*)d_out;

    cudaFuncSetAttribute(recurrence_kernel,
                         cudaFuncAttributeMaxDynamicSharedMemorySize, SMEM_BYTES);
    cudaFuncSetAttribute(xgemm_kernel,
                         cudaFuncAttributeMaxDynamicSharedMemorySize, XG_SMEM);

    init_kernel<<<64, 256>>>();
    conv_a_kernel<<<2048 * 32 / 8, 256>>>(tokens, emb);
    conv_b_kernel<<<32 * 256 / 8, 256>>>(Wi);

    dim3 xg(256, 32);
    xgemm_kernel<<<xg, 256, XG_SMEM>>>(bias);

    recurrence_kernel<<<NBLK, 256, SMEM_BYTES>>>(Wh);

    classifier_kernel<<<BB, 128>>>(Wd, bd, out);
}

// round 15
// speedup vs baseline: 1.2890x; 1.0024x over previous
#include <cuda_runtime.h>
#include <cuda_bf16.h>
#include <cuda_fp16.h>
#include <math.h>

#define BB 64
#define TT 512
#define EE 512
#define HH 1024
#define GG 4096   // 4*H
#define CC 4
#define NBLK 128  // persistent recurrence blocks (8 units each)

// ---------------------------------------------------------------------------
// Global scratch (static device arrays — no runtime allocation)
// ---------------------------------------------------------------------------
__device__ float g_xp[(size_t)TT * BB * GG];          // [T][B][4H] input projections
__device__ float g_h[BB * HH];                        // final hidden state
// h staged as fp16 MMA A-fragments: [buf][ktile 64][mtile 4][lane 32] x 16B
__device__ uint4 g_hstage[2][64 * 4 * 32];
__device__ unsigned g_bar;                            // global barrier counter

// xproj operands pre-converted to MMA fragment layout (bf16 hi/lo)
__device__ uint4 g_afrag[(size_t)2048 * 32 * 2 * 32];   // 64 MB
__device__ uint4 g_bfrag[(size_t)32 * 256 * 2 * 32];    // 8 MB

// ---------------------------------------------------------------------------
// helpers
// ---------------------------------------------------------------------------
__device__ __forceinline__ void cpasync16(unsigned dst, const void* src) {
    asm volatile("cp.async.cg.shared.global [%0], [%1], 16;" :: "r"(dst), "l"(src));
}
__device__ __forceinline__ uint4 lds128(unsigned addr) {
    uint4 v;
    asm volatile("ld.shared.v4.u32 {%0,%1,%2,%3}, [%4];"
                 : "=r"(v.x), "=r"(v.y), "=r"(v.z), "=r"(v.w) : "r"(addr));
    return v;
}
__device__ __forceinline__ uint4 ldgcg128(const uint4* p) {
    uint4 v;
    asm volatile("ld.global.cg.v4.u32 {%0,%1,%2,%3}, [%4];"
                 : "=r"(v.x), "=r"(v.y), "=r"(v.z), "=r"(v.w) : "l"(p));
    return v;
}
__device__ __forceinline__ void mma16816(float* d, const uint4& a, unsigned b0, unsigned b1) {
    asm volatile("mma.sync.aligned.m16n8k16.row.col.f32.bf16.bf16.f32 "
                 "{%0,%1,%2,%3}, {%4,%5,%6,%7}, {%8,%9}, {%0,%1,%2,%3};"
                 : "+f"(d[0]), "+f"(d[1]), "+f"(d[2]), "+f"(d[3])
                 : "r"(a.x), "r"(a.y), "r"(a.z), "r"(a.w), "r"(b0), "r"(b1));
}
__device__ __forceinline__ void mma16816h(float* d, const uint4& a, unsigned b0, unsigned b1) {
    asm volatile("mma.sync.aligned.m16n8k16.row.col.f32.f16.f16.f32 "
                 "{%0,%1,%2,%3}, {%4,%5,%6,%7}, {%8,%9}, {%0,%1,%2,%3};"
                 : "+f"(d[0]), "+f"(d[1]), "+f"(d[2]), "+f"(d[3])
                 : "r"(a.x), "r"(a.y), "r"(a.z), "r"(a.w), "r"(b0), "r"(b1));
}
__device__ __forceinline__ unsigned pack_hi(float x0, float x1) {
    unsigned h0 = (unsigned)__bfloat16_as_ushort(__float2bfloat16(x0));
    unsigned h1 = (unsigned)__bfloat16_as_ushort(__float2bfloat16(x1));
    return h0 | (h1 << 16);
}
__device__ __forceinline__ unsigned pack_lo(float x0, float x1) {
    float r0 = x0 - __bfloat162float(__float2bfloat16(x0));
    float r1 = x1 - __bfloat162float(__float2bfloat16(x1));
    unsigned h0 = (unsigned)__bfloat16_as_ushort(__float2bfloat16(r0));
    unsigned h1 = (unsigned)__bfloat16_as_ushort(__float2bfloat16(r1));
    return h0 | (h1 << 16);
}

// ---------------------------------------------------------------------------
// init
// ---------------------------------------------------------------------------
__global__ void init_kernel() {
    int i = blockIdx.x * blockDim.x + threadIdx.x;
    if (i == 0) g_bar = 0u;
    if (i < 64 * 4 * 32) g_hstage[0][i] = make_uint4(0u, 0u, 0u, 0u);
}

// ---------------------------------------------------------------------------
// conv_a: gather emb rows, convert to bf16 hi/lo A-fragment layout. (validated)
// ---------------------------------------------------------------------------
__global__ __launch_bounds__(256) void conv_a_kernel(
        const int* __restrict__ tokens, const float* __restrict__ emb) {
    int gw = (blockIdx.x * 256 + threadIdx.x) >> 5;
    int lane = threadIdx.x & 31;
    int mt = gw >> 5;          // 0..2047
    int kt = gw & 31;          // 0..31
    int t_ = mt >> 2;
    int b0_ = ((mt & 3) << 4) + (lane >> 2);
    int b1_ = b0_ + 8;
    const float* er0 = emb + (size_t)tokens[b0_ * TT + t_] * EE + kt * 16;
    const float* er1 = emb + (size_t)tokens[b1_ * TT + t_] * EE + kt * 16;

    unsigned hi[4], lo[4];
#pragma unroll
    for (int r2 = 0; r2 < 4; r2++) {
        const float* er = (r2 & 1) ? er1 : er0;
        int kc0 = ((lane & 3) << 1) + ((r2 >> 1) << 3);
        float x0 = er[kc0], x1 = er[kc0 + 1];
        hi[r2] = pack_hi(x0, x1);
        lo[r2] = pack_lo(x0, x1);
    }
    size_t base = ((size_t)(mt * 32 + kt) * 2) * 32 + lane;
    g_afrag[base]      = make_uint4(hi[0], hi[1], hi[2], hi[3]);
    g_afrag[base + 32] = make_uint4(lo[0], lo[1], lo[2], lo[3]);
}

// ---------------------------------------------------------------------------
// conv_b: Wi -> bf16 hi/lo B-fragment layout. (validated)
// ---------------------------------------------------------------------------
__global__ __launch_bounds__(256) void conv_b_kernel(const float* __restrict__ Wi) {
    int gw = (blockIdx.x * 256 + threadIdx.x) >> 5;
    int lane = threadIdx.x & 31;
    int kt = gw >> 8;          // 0..31
    int nt = gw & 255;         // 0..255

    unsigned hi[4], lo[4];
#pragma unroll
    for (int w = 0; w < 4; w++) {
        int n  = ((w >> 1) << 3) + (lane >> 2);
        int kc0 = ((lane & 3) << 1) + ((w & 1) << 3);
        const float* p = Wi + (size_t)(kt * 16 + kc0) * GG + nt * 16 + n;
        float x0 = p[0], x1 = p[GG];
        hi[w] = pack_hi(x0, x1);
        lo[w] = pack_lo(x0, x1);
    }
    size_t base = ((size_t)(kt * 256 + nt) * 2) * 32 + lane;
    g_bfrag[base]      = make_uint4(hi[0], hi[1], hi[2], hi[3]);
    g_bfrag[base + 32] = make_uint4(lo[0], lo[1], lo[2], lo[3]);
}

// ---------------------------------------------------------------------------
// xgemm: XP = X @ Wi + bias via bf16 split-3 MMA. 128x128 tile. (validated)
// ---------------------------------------------------------------------------
#define XG_ABUF 16384
#define XG_BOFF 32768
#define XG_SMEM 65536

__global__ __launch_bounds__(256) void xgemm_kernel(const float* __restrict__ bias) {
    extern __shared__ char smem[];
    const unsigned smem_u32 = (unsigned)__cvta_generic_to_shared(smem);
    const int tid = threadIdx.x;
    const int warp = tid >> 5, lane = tid & 31;
    const int mq = warp & 1;
    const int nq = warp >> 1;
    const int bx = blockIdx.x, by = blockIdx.y;

    const bool isA = tid < 128;
    const int amt = (tid & 127) >> 4;
    const int sub = tid & 15;

    float acc[4][4][4];
#pragma unroll
    for (int i = 0; i < 4; i++)
#pragma unroll
        for (int j = 0; j < 4; j++)
#pragma unroll
            for (int q = 0; q < 4; q++) acc[i][j][q] = 0.f;

#pragma unroll
    for (int j = 0; j < 8; j++) {
        int q = sub * 8 + j;
        int kt = q >> 6, hl = (q >> 5) & 1, ln = q & 31;
        unsigned dst; const uint4* src;
        if (isA) {
            dst = smem_u32 + ((amt * 2 + kt) * 2 + hl) * 512 + ln * 16;
            src = g_afrag + (((size_t)(bx * 8 + amt) * 32 + kt) * 2 + hl) * 32 + ln;
        } else {
            dst = smem_u32 + XG_BOFF + ((kt * 8 + amt) * 2 + hl) * 512 + ln * 16;
            src = g_bfrag + (((size_t)kt * 256 + (by * 8 + amt)) * 2 + hl) * 32 + ln;
        }
        cpasync16(dst, src);
    }
    asm volatile("cp.async.commit_group;");

    for (int c = 0; c < 16; c++) {
        if (c < 15) {
            int buf = (c + 1) & 1;
#pragma unroll
            for (int j = 0; j < 8; j++) {
                int q = sub * 8 + j;
                int kt = q >> 6, hl = (q >> 5) & 1, ln = q & 31;
                int ktg = (c + 1) * 2 + kt;
                unsigned dst; const uint4* src;
                if (isA) {
                    dst = smem_u32 + buf * XG_ABUF + ((amt * 2 + kt) * 2 + hl) * 512 + ln * 16;
                    src = g_afrag + (((size_t)(bx * 8 + amt) * 32 + ktg) * 2 + hl) * 32 + ln;
                } else {
                    dst = smem_u32 + XG_BOFF + buf * XG_ABUF + ((kt * 8 + amt) * 2 + hl) * 512 + ln * 16;
                    src = g_bfrag + (((size_t)ktg * 256 + (by * 8 + amt)) * 2 + hl) * 32 + ln;
                }
                cpasync16(dst, src);
            }
            asm volatile("cp.async.commit_group;");
            asm volatile("cp.async.wait_group 1;");
        } else {
            asm volatile("cp.async.wait_group 0;");
        }
        __syncthreads();

        int buf = c & 1;
#pragma unroll
        for (int kt = 0; kt < 2; kt++) {
            unsigned bb0 = smem_u32 + XG_BOFF + buf * XG_ABUF
                         + ((kt * 8 + nq * 2) * 2) * 512 + (lane << 4);
            uint4 bh0 = lds128(bb0);
            uint4 bl0 = lds128(bb0 + 512);
            uint4 bh1 = lds128(bb0 + 1024);
            uint4 bl1 = lds128(bb0 + 1536);
#pragma unroll
            for (int mi = 0; mi < 4; mi++) {
                unsigned ab = smem_u32 + buf * XG_ABUF
                            + (((mq * 4 + mi) * 2 + kt) * 2) * 512 + (lane << 4);
                uint4 ah = lds128(ab);
                uint4 al = lds128(ab + 512);
                mma16816(acc[mi][0], ah, bh0.x, bh0.y);
                mma16816(acc[mi][0], ah, bl0.x, bl0.y);
                mma16816(acc[mi][0], al, bh0.x, bh0.y);
                mma16816(acc[mi][1], ah, bh0.z, bh0.w);
                mma16816(acc[mi][1], ah, bl0.z, bl0.w);
                mma16816(acc[mi][1], al, bh0.z, bh0.w);
                mma16816(acc[mi][2], ah, bh1.x, bh1.y);
                mma16816(acc[mi][2], ah, bl1.x, bl1.y);
                mma16816(acc[mi][2], al, bh1.x, bh1.y);
                mma16816(acc[mi][3], ah, bh1.z, bh1.w);
                mma16816(acc[mi][3], ah, bl1.z, bl1.w);
                mma16816(acc[mi][3], al, bh1.z, bh1.w);
            }
        }
        __syncthreads();
    }

    const int g = lane >> 2, tq = lane & 3;
#pragma unroll
    for (int mi = 0; mi < 4; mi++) {
        int row = bx * 128 + mq * 64 + mi * 16 + g;
#pragma unroll
        for (int nj = 0; nj < 4; nj++) {
            int col = by * 128 + nq * 32 + nj * 8 + tq * 2;
            float b0 = bias[col], b1 = bias[col + 1];
            float* p0 = g_xp + (size_t)row * GG + col;
            float* p1 = g_xp + (size_t)(row + 8) * GG + col;
            *(float2*)p0 = make_float2(acc[mi][nj][0] + b0, acc[mi][nj][1] + b1);
            *(float2*)p1 = make_float2(acc[mi][nj][2] + b0, acc[mi][nj][3] + b1);
        }
    }
}

// ---------------------------------------------------------------------------
// Persistent recurrence kernel: direct global->register A loads, software-
// pipelined 2 deep across chunks; xp double-buffered and prefetched one step
// ahead (xp is h-independent, so the prefetch legally crosses the barrier).
// Warp kh owns ktiles c*8+kh.
// Smem:
//   [0, 65536)          Wh B-fragments (fp16, single plane, 64 KB)
//   [65536, 135168)     8 partial-D regions [kh][64][34] f32 (dedicated)
//   [135168, 153600)    xp staging, 2 buffers of [64][36] f32
// ---------------------------------------------------------------------------
#define ABUF_BYTES 16384
#define PART_STRIDE 34
#define PART_RB (64 * PART_STRIDE * 4)    // 8704 per region
#define WOFF 0
#define POFF 65536
#define XPOFF 135168
#define XP_STRIDE 36
#define XPBUF (64 * XP_STRIDE * 4)        // 9216 per buffer
#define SMEM_BYTES (XPOFF + 2 * XPBUF)    // 153600

__global__ __launch_bounds__(256, 1) void recurrence_kernel(const float* __restrict__ Wh) {
    extern __shared__ char smem[];
    const int tid  = threadIdx.x;
    const int blk  = blockIdx.x;
    const int kh   = tid >> 5;       // warp id = K-slice id
    const int lane = tid & 31;
    const unsigned smem_u32 = (unsigned)__cvta_generic_to_shared(smem);

    // one-time: stage Wh slice as fp16 B fragments (single plane)
    for (int idx = tid; idx < 32 * 1024; idx += 256) {
        int k = idx >> 5, n = idx & 31;
        int gcol = ((n >> 3) << 10) + (blk << 3) + (n & 7);
        float w = Wh[(size_t)k * GG + gcol];
        int kc = k & 15;
        int ln = ((n & 7) << 2) + ((kc & 7) >> 1);
        int by = (((n >> 3) & 1) << 3) + (((kc >> 3) & 1) << 2) + ((kc & 1) << 1);
        int base = WOFF + (((k >> 4) << 1) + (n >> 4)) * 512 + (ln << 4) + by;
        *(__half*)(smem + base) = __float2half_rn(w);
    }
    __syncthreads();

    const int ub = tid & 63;
    const int up = tid >> 6;       // 0..3; thread owns adjacent units 2up, 2up+1
    float creg[2] = {0.f, 0.f};

    // prefetch xp[0] into buffer 0
    {
#pragma unroll
        for (int e = 0; e < 2; e++) {
            int idx = tid * 2 + e;
            int b_ = idx >> 3, gate = (idx >> 1) & 3, half = idx & 1;
            const float* s = g_xp + (size_t)b_ * GG
                           + gate * HH + (blk << 3) + half * 4;
            unsigned d = smem_u32 + XPOFF
                       + (b_ * XP_STRIDE + gate * 8 + half * 4) * 4;
            cpasync16(d, s);
        }
        asm volatile("cp.async.commit_group;");
    }

    for (int t = 0; t < TT; t++) {
        const char* hsrc = (const char*)g_hstage[t & 1];

        // prefetch xp[t+1] into the other buffer (overlaps entire GEMM;
        // independent of h, so it may run across the next barrier too)
        if (t + 1 < TT) {
#pragma unroll
            for (int e = 0; e < 2; e++) {
                int idx = tid * 2 + e;
                int b_ = idx >> 3, gate = (idx >> 1) & 3, half = idx & 1;
                const float* s = g_xp + ((size_t)(t + 1) * BB + b_) * GG
                               + gate * HH + (blk << 3) + half * 4;
                unsigned d = smem_u32 + XPOFF + ((t + 1) & 1) * XPBUF
                           + (b_ * XP_STRIDE + gate * 8 + half * 4) * 4;
                cpasync16(d, s);
            }
        }
        asm volatile("cp.async.commit_group;");

        float acc[4][4][4];
#pragma unroll
        for (int i = 0; i < 4; i++)
#pragma unroll
            for (int j = 0; j < 4; j++)
#pragma unroll
                for (int q = 0; q < 4; q++) acc[i][j][q] = 0.f;

        // software-pipelined GEMM: prefetch chunk c+1's A while doing MMA(c)
        uint4 acur[4], anxt[4];
#pragma unroll
        for (int mt = 0; mt < 4; mt++) {
            size_t byteoff = (size_t)(kh * 4 + mt) * 512 + (lane << 4);
            acur[mt] = ldgcg128((const uint4*)(hsrc + byteoff));
        }
#pragma unroll
        for (int c = 0; c < 8; c++) {
            if (c < 7) {
#pragma unroll
                for (int mt = 0; mt < 4; mt++) {
                    size_t byteoff = (size_t)(c + 1) * ABUF_BYTES
                                   + (kh * 4 + mt) * 512 + (lane << 4);
                    anxt[mt] = ldgcg128((const uint4*)(hsrc + byteoff));
                }
            }
            const int ktg = c * 8 + kh;
            unsigned bb0 = smem_u32 + WOFF + (ktg * 2 + 0) * 512 + (lane << 4);
            unsigned bb1 = smem_u32 + WOFF + (ktg * 2 + 1) * 512 + (lane << 4);
            uint4 b0 = lds128(bb0);
            uint4 b1 = lds128(bb1);
#pragma unroll
            for (int mt = 0; mt < 4; mt++) {
                mma16816h(acc[mt][0], acur[mt], b0.x, b0.y);
                mma16816h(acc[mt][1], acur[mt], b0.z, b0.w);
                mma16816h(acc[mt][2], acur[mt], b1.x, b1.y);
                mma16816h(acc[mt][3], acur[mt], b1.z, b1.w);
            }
#pragma unroll
            for (int mt = 0; mt < 4; mt++) acur[mt] = anxt[mt];
        }

        // ---- write per-kh partial D (dedicated region, no aliasing) ----
        {
            float* P = (float*)(smem + POFF + kh * PART_RB);
            int g = lane >> 2, tq = lane & 3;
#pragma unroll
            for (int mt = 0; mt < 4; mt++) {
#pragma unroll
                for (int nj = 0; nj < 4; nj++) {
                    int row = mt * 16 + g;
                    int col = nj * 8 + tq * 2;
                    *(float2*)&P[row * PART_STRIDE + col] =
                        make_float2(acc[mt][nj][0], acc[mt][nj][1]);
                    *(float2*)&P[(row + 8) * PART_STRIDE + col] =
                        make_float2(acc[mt][nj][2], acc[mt][nj][3]);
                }
            }
        }
        asm volatile("cp.async.wait_group 1;");   // xp[t] ready (older group)
        __syncthreads();                          // partials visible block-wide

        // ---- pointwise LSTM update: adjacent units 2up, 2up+1 ----
        {
            const float* xps = (const float*)(smem + XPOFF + (t & 1) * XPBUF);
            char* hdst = (char*)g_hstage[(t + 1) & 1];
            float hn[2];
#pragma unroll
            for (int pi = 0; pi < 2; pi++) {
                int p = 2 * up + pi;
                float gv[4];
#pragma unroll
                for (int type = 0; type < 4; type++) {
                    int n = type * 8 + p;
                    float s = xps[ub * XP_STRIDE + n];
#pragma unroll
                    for (int r = 0; r < 8; r++)
                        s += ((const float*)(smem + POFF + r * PART_RB))[ub * PART_STRIDE + n];
                    gv[type] = s;
                }
                float si = 1.f / (1.f + expf(-gv[0]));
                float sf = 1.f / (1.f + expf(-gv[1]));
                float tg = tanhf(gv[2]);
                float so = 1.f / (1.f + expf(-gv[3]));
                float cn = fmaf(sf, creg[pi], si * tg);
                creg[pi] = cn;
                hn[pi] = so * tanhf(cn);
                if (t == TT - 1) g_h[ub * HH + (blk << 3) + p] = hn[pi];
            }

            // packed u32 store: units 2up (lo half) and 2up+1 (hi half)
            {
                int unit0 = (blk << 3) + 2 * up;      // even unit
                int r = ub & 15, mt = ub >> 4;
                int kc = unit0 & 15, ktile = unit0 >> 4;
                int ln  = ((r & 7) << 2) + ((kc & 7) >> 1);
                int reg = (((kc >> 3) & 1) << 1) + ((r >> 3) & 1);
                int off = (ktile * 4 + mt) * 512 + (ln << 4) + (reg << 2);
                unsigned h0 = (unsigned)__half_as_ushort(__float2half_rn(hn[0]));
                unsigned h1 = (unsigned)__half_as_ushort(__float2half_rn(hn[1]));
                *(unsigned*)(hdst + off) = h0 | (h1 << 16);
            }
        }

        // ---- single-counter grid barrier with backoff (validated) ----
        __threadfence();
        __syncthreads();
        if (tid == 0) {
            atomicAdd(&g_bar, 1u);
            unsigned tgt = (unsigned)(NBLK * (t + 1));
            while (*((volatile unsigned*)&g_bar) < tgt) __nanosleep(32);
        }
        __syncthreads();
    }
}

// ---------------------------------------------------------------------------
// classifier: 64 blocks (one per batch), 128 threads.
// ---------------------------------------------------------------------------
__global__ __launch_bounds__(128) void classifier_kernel(
        const float* __restrict__ Wd, const float* __restrict__ bd,
        float* __restrict__ out) {
    __shared__ float4 red[4];
    int b = blockIdx.x, tid = threadIdx.x;
    int lane = tid & 31, warp = tid >> 5;
    float4 a = make_float4(0.f, 0.f, 0.f, 0.f);
    for (int k = tid; k < HH; k += 128) {
        float h = g_h[b * HH + k];
        float4 w = *(const float4*)(Wd + k * CC);
        a.x = fmaf(h, w.x, a.x); a.y = fmaf(h, w.y, a.y);
        a.z = fmaf(h, w.z, a.z); a.w = fmaf(h, w.w, a.w);
    }
#pragma unroll
    for (int s = 16; s > 0; s >>= 1) {
        a.x += __shfl_xor_sync(0xffffffffu, a.x, s);
        a.y += __shfl_xor_sync(0xffffffffu, a.y, s);
        a.z += __shfl_xor_sync(0xffffffffu, a.z, s);
        a.w += __shfl_xor_sync(0xffffffffu, a.w, s);
    }
    if (lane == 0) red[warp] = a;
    __syncthreads();
    if (tid == 0) {
        float4 s = red[0];
        s.x += red[1].x + red[2].x + red[3].x;
        s.y += red[1].y + red[2].y + red[3].y;
        s.z += red[1].z + red[2].z + red[3].z;
        s.w += red[1].w + red[2].w + red[3].w;
        out[b * CC + 0] = s.x + bd[0];
        out[b * CC + 1] = s.y + bd[1];
        out[b * CC + 2] = s.z + bd[2];
        out[b * CC + 3] = s.w + bd[3];
    }
}

// ---------------------------------------------------------------------------
// launch: 6 graph nodes
// ---------------------------------------------------------------------------
extern "C" void kernel_launch(void* const* d_in, const int* in_sizes, int n_in,
                              void* d_out, int out_size) {
    const int*   tokens = (const int*)d_in[0];
    const float* emb    = (const float*)d_in[1];
    const float* Wi     = (const float*)d_in[2];
    const float* Wh     = (const float*)d_in[3];
    const float* bias   = (const float*)d_in[4];
    const float* Wd     = (const float*)d_in[5];
    const float* bd     = (const float*)d_in[6];
    float* out = (float*)d_out;

    cudaFuncSetAttribute(recurrence_kernel,
                         cudaFuncAttributeMaxDynamicSharedMemorySize, SMEM_BYTES);
    cudaFuncSetAttribute(xgemm_kernel,
                         cudaFuncAttributeMaxDynamicSharedMemorySize, XG_SMEM);

    init_kernel<<<64, 256>>>();
    conv_a_kernel<<<2048 * 32 / 8, 256>>>(tokens, emb);
    conv_b_kernel<<<32 * 256 / 8, 256>>>(Wi);

    dim3 xg(256, 32);
    xgemm_kernel<<<xg, 256, XG_SMEM>>>(bias);

    recurrence_kernel<<<NBLK, 256, SMEM_BYTES>>>(Wh);

    classifier_kernel<<<BB, 128>>>(Wd, bd, out);
}

// round 16
// speedup vs baseline: 1.3151x; 1.0203x over previous
#include <cuda_runtime.h>
#include <cuda_bf16.h>
#include <cuda_fp16.h>
#include <math.h>

#define BB 64
#define TT 512
#define EE 512
#define HH 1024
#define GG 4096   // 4*H
#define CC 4
#define NBLK 128  // persistent recurrence blocks (8 units each)

// ---------------------------------------------------------------------------
// Global scratch (static device arrays — no runtime allocation)
// ---------------------------------------------------------------------------
__device__ float g_xp[(size_t)TT * BB * GG];          // [T][B][4H] input projections
__device__ float g_h[BB * HH];                        // final hidden state
// h staged as fp16 MMA A-fragments: [buf][ktile 64][mtile 4][lane 32] x 16B
__device__ uint4 g_hstage[2][64 * 4 * 32];
__device__ unsigned g_bar;                            // global barrier counter

// xproj operands pre-converted to MMA fragment layout (bf16 hi/lo)
__device__ uint4 g_afrag[(size_t)2048 * 32 * 2 * 32];   // 64 MB
__device__ uint4 g_bfrag[(size_t)32 * 256 * 2 * 32];    // 8 MB

// ---------------------------------------------------------------------------
// helpers
// ---------------------------------------------------------------------------
__device__ __forceinline__ void cpasync16(unsigned dst, const void* src) {
    asm volatile("cp.async.cg.shared.global [%0], [%1], 16;" :: "r"(dst), "l"(src));
}
__device__ __forceinline__ uint4 lds128(unsigned addr) {
    uint4 v;
    asm volatile("ld.shared.v4.u32 {%0,%1,%2,%3}, [%4];"
                 : "=r"(v.x), "=r"(v.y), "=r"(v.z), "=r"(v.w) : "r"(addr));
    return v;
}
__device__ __forceinline__ uint4 ldgcg128(const uint4* p) {
    uint4 v;
    asm volatile("ld.global.cg.v4.u32 {%0,%1,%2,%3}, [%4];"
                 : "=r"(v.x), "=r"(v.y), "=r"(v.z), "=r"(v.w) : "l"(p));
    return v;
}
__device__ __forceinline__ void mma16816(float* d, const uint4& a, unsigned b0, unsigned b1) {
    asm volatile("mma.sync.aligned.m16n8k16.row.col.f32.bf16.bf16.f32 "
                 "{%0,%1,%2,%3}, {%4,%5,%6,%7}, {%8,%9}, {%0,%1,%2,%3};"
                 : "+f"(d[0]), "+f"(d[1]), "+f"(d[2]), "+f"(d[3])
                 : "r"(a.x), "r"(a.y), "r"(a.z), "r"(a.w), "r"(b0), "r"(b1));
}
__device__ __forceinline__ void mma16816h(float* d, const uint4& a, unsigned b0, unsigned b1) {
    asm volatile("mma.sync.aligned.m16n8k16.row.col.f32.f16.f16.f32 "
                 "{%0,%1,%2,%3}, {%4,%5,%6,%7}, {%8,%9}, {%0,%1,%2,%3};"
                 : "+f"(d[0]), "+f"(d[1]), "+f"(d[2]), "+f"(d[3])
                 : "r"(a.x), "r"(a.y), "r"(a.z), "r"(a.w), "r"(b0), "r"(b1));
}
__device__ __forceinline__ unsigned pack_hi(float x0, float x1) {
    unsigned h0 = (unsigned)__bfloat16_as_ushort(__float2bfloat16(x0));
    unsigned h1 = (unsigned)__bfloat16_as_ushort(__float2bfloat16(x1));
    return h0 | (h1 << 16);
}
__device__ __forceinline__ unsigned pack_lo(float x0, float x1) {
    float r0 = x0 - __bfloat162float(__float2bfloat16(x0));
    float r1 = x1 - __bfloat162float(__float2bfloat16(x1));
    unsigned h0 = (unsigned)__bfloat16_as_ushort(__float2bfloat16(r0));
    unsigned h1 = (unsigned)__bfloat16_as_ushort(__float2bfloat16(r1));
    return h0 | (h1 << 16);
}

// ---------------------------------------------------------------------------
// init
// ---------------------------------------------------------------------------
__global__ void init_kernel() {
    int i = blockIdx.x * blockDim.x + threadIdx.x;
    if (i == 0) g_bar = 0u;
    if (i < 64 * 4 * 32) g_hstage[0][i] = make_uint4(0u, 0u, 0u, 0u);
}

// ---------------------------------------------------------------------------
// conv_a: gather emb rows, convert to bf16 hi/lo A-fragment layout. (validated)
// ---------------------------------------------------------------------------
__global__ __launch_bounds__(256) void conv_a_kernel(
        const int* __restrict__ tokens, const float* __restrict__ emb) {
    int gw = (blockIdx.x * 256 + threadIdx.x) >> 5;
    int lane = threadIdx.x & 31;
    int mt = gw >> 5;          // 0..2047
    int kt = gw & 31;          // 0..31
    int t_ = mt >> 2;
    int b0_ = ((mt & 3) << 4) + (lane >> 2);
    int b1_ = b0_ + 8;
    const float* er0 = emb + (size_t)tokens[b0_ * TT + t_] * EE + kt * 16;
    const float* er1 = emb + (size_t)tokens[b1_ * TT + t_] * EE + kt * 16;

    unsigned hi[4], lo[4];
#pragma unroll
    for (int r2 = 0; r2 < 4; r2++) {
        const float* er = (r2 & 1) ? er1 : er0;
        int kc0 = ((lane & 3) << 1) + ((r2 >> 1) << 3);
        float x0 = er[kc0], x1 = er[kc0 + 1];
        hi[r2] = pack_hi(x0, x1);
        lo[r2] = pack_lo(x0, x1);
    }
    size_t base = ((size_t)(mt * 32 + kt) * 2) * 32 + lane;
    g_afrag[base]      = make_uint4(hi[0], hi[1], hi[2], hi[3]);
    g_afrag[base + 32] = make_uint4(lo[0], lo[1], lo[2], lo[3]);
}

// ---------------------------------------------------------------------------
// conv_b: Wi -> bf16 hi/lo B-fragment layout. (validated)
// ---------------------------------------------------------------------------
__global__ __launch_bounds__(256) void conv_b_kernel(const float* __restrict__ Wi) {
    int gw = (blockIdx.x * 256 + threadIdx.x) >> 5;
    int lane = threadIdx.x & 31;
    int kt = gw >> 8;          // 0..31
    int nt = gw & 255;         // 0..255

    unsigned hi[4], lo[4];
#pragma unroll
    for (int w = 0; w < 4; w++) {
        int n  = ((w >> 1) << 3) + (lane >> 2);
        int kc0 = ((lane & 3) << 1) + ((w & 1) << 3);
        const float* p = Wi + (size_t)(kt * 16 + kc0) * GG + nt * 16 + n;
        float x0 = p[0], x1 = p[GG];
        hi[w] = pack_hi(x0, x1);
        lo[w] = pack_lo(x0, x1);
    }
    size_t base = ((size_t)(kt * 256 + nt) * 2) * 32 + lane;
    g_bfrag[base]      = make_uint4(hi[0], hi[1], hi[2], hi[3]);
    g_bfrag[base + 32] = make_uint4(lo[0], lo[1], lo[2], lo[3]);
}

// ---------------------------------------------------------------------------
// xgemm: XP = X @ Wi + bias via bf16 split-3 MMA. 128x128 tile. (validated)
// ---------------------------------------------------------------------------
#define XG_ABUF 16384
#define XG_BOFF 32768
#define XG_SMEM 65536

__global__ __launch_bounds__(256) void xgemm_kernel(const float* __restrict__ bias) {
    extern __shared__ char smem[];
    const unsigned smem_u32 = (unsigned)__cvta_generic_to_shared(smem);
    const int tid = threadIdx.x;
    const int warp = tid >> 5, lane = tid & 31;
    const int mq = warp & 1;
    const int nq = warp >> 1;
    const int bx = blockIdx.x, by = blockIdx.y;

    const bool isA = tid < 128;
    const int amt = (tid & 127) >> 4;
    const int sub = tid & 15;

    float acc[4][4][4];
#pragma unroll
    for (int i = 0; i < 4; i++)
#pragma unroll
        for (int j = 0; j < 4; j++)
#pragma unroll
            for (int q = 0; q < 4; q++) acc[i][j][q] = 0.f;

#pragma unroll
    for (int j = 0; j < 8; j++) {
        int q = sub * 8 + j;
        int kt = q >> 6, hl = (q >> 5) & 1, ln = q & 31;
        unsigned dst; const uint4* src;
        if (isA) {
            dst = smem_u32 + ((amt * 2 + kt) * 2 + hl) * 512 + ln * 16;
            src = g_afrag + (((size_t)(bx * 8 + amt) * 32 + kt) * 2 + hl) * 32 + ln;
        } else {
            dst = smem_u32 + XG_BOFF + ((kt * 8 + amt) * 2 + hl) * 512 + ln * 16;
            src = g_bfrag + (((size_t)kt * 256 + (by * 8 + amt)) * 2 + hl) * 32 + ln;
        }
        cpasync16(dst, src);
    }
    asm volatile("cp.async.commit_group;");

    for (int c = 0; c < 16; c++) {
        if (c < 15) {
            int buf = (c + 1) & 1;
#pragma unroll
            for (int j = 0; j < 8; j++) {
                int q = sub * 8 + j;
                int kt = q >> 6, hl = (q >> 5) & 1, ln = q & 31;
                int ktg = (c + 1) * 2 + kt;
                unsigned dst; const uint4* src;
                if (isA) {
                    dst = smem_u32 + buf * XG_ABUF + ((amt * 2 + kt) * 2 + hl) * 512 + ln * 16;
                    src = g_afrag + (((size_t)(bx * 8 + amt) * 32 + ktg) * 2 + hl) * 32 + ln;
                } else {
                    dst = smem_u32 + XG_BOFF + buf * XG_ABUF + ((kt * 8 + amt) * 2 + hl) * 512 + ln * 16;
                    src = g_bfrag + (((size_t)ktg * 256 + (by * 8 + amt)) * 2 + hl) * 32 + ln;
                }
                cpasync16(dst, src);
            }
            asm volatile("cp.async.commit_group;");
            asm volatile("cp.async.wait_group 1;");
        } else {
            asm volatile("cp.async.wait_group 0;");
        }
        __syncthreads();

        int buf = c & 1;
#pragma unroll
        for (int kt = 0; kt < 2; kt++) {
            unsigned bb0 = smem_u32 + XG_BOFF + buf * XG_ABUF
                         + ((kt * 8 + nq * 2) * 2) * 512 + (lane << 4);
            uint4 bh0 = lds128(bb0);
            uint4 bl0 = lds128(bb0 + 512);
            uint4 bh1 = lds128(bb0 + 1024);
            uint4 bl1 = lds128(bb0 + 1536);
#pragma unroll
            for (int mi = 0; mi < 4; mi++) {
                unsigned ab = smem_u32 + buf * XG_ABUF
                            + (((mq * 4 + mi) * 2 + kt) * 2) * 512 + (lane << 4);
                uint4 ah = lds128(ab);
                uint4 al = lds128(ab + 512);
                mma16816(acc[mi][0], ah, bh0.x, bh0.y);
                mma16816(acc[mi][0], ah, bl0.x, bl0.y);
                mma16816(acc[mi][0], al, bh0.x, bh0.y);
                mma16816(acc[mi][1], ah, bh0.z, bh0.w);
                mma16816(acc[mi][1], ah, bl0.z, bl0.w);
                mma16816(acc[mi][1], al, bh0.z, bh0.w);
                mma16816(acc[mi][2], ah, bh1.x, bh1.y);
                mma16816(acc[mi][2], ah, bl1.x, bl1.y);
                mma16816(acc[mi][2], al, bh1.x, bh1.y);
                mma16816(acc[mi][3], ah, bh1.z, bh1.w);
                mma16816(acc[mi][3], ah, bl1.z, bl1.w);
                mma16816(acc[mi][3], al, bh1.z, bh1.w);
            }
        }
        __syncthreads();
    }

    const int g = lane >> 2, tq = lane & 3;
#pragma unroll
    for (int mi = 0; mi < 4; mi++) {
        int row = bx * 128 + mq * 64 + mi * 16 + g;
#pragma unroll
        for (int nj = 0; nj < 4; nj++) {
            int col = by * 128 + nq * 32 + nj * 8 + tq * 2;
            float b0 = bias[col], b1 = bias[col + 1];
            float* p0 = g_xp + (size_t)row * GG + col;
            float* p1 = g_xp + (size_t)(row + 8) * GG + col;
            *(float2*)p0 = make_float2(acc[mi][nj][0] + b0, acc[mi][nj][1] + b1);
            *(float2*)p1 = make_float2(acc[mi][nj][2] + b0, acc[mi][nj][3] + b1);
        }
    }
}

// ---------------------------------------------------------------------------
// Persistent recurrence kernel: direct global->register A loads (2-deep SW
// pipeline), xp double-buffered one step ahead. Grid sync via release/acquire
// single-counter barrier -- NO per-thread __threadfence.
// Warp kh owns ktiles c*8+kh.
// Smem:
//   [0, 65536)          Wh B-fragments (fp16, single plane, 64 KB)
//   [65536, 135168)     8 partial-D regions [kh][64][34] f32 (dedicated)
//   [135168, 153600)    xp staging, 2 buffers of [64][36] f32
// ---------------------------------------------------------------------------
#define ABUF_BYTES 16384
#define PART_STRIDE 34
#define PART_RB (64 * PART_STRIDE * 4)    // 8704 per region
#define WOFF 0
#define POFF 65536
#define XPOFF 135168
#define XP_STRIDE 36
#define XPBUF (64 * XP_STRIDE * 4)        // 9216 per buffer
#define SMEM_BYTES (XPOFF + 2 * XPBUF)    // 153600

__global__ __launch_bounds__(256, 1) void recurrence_kernel(const float* __restrict__ Wh) {
    extern __shared__ char smem[];
    const int tid  = threadIdx.x;
    const int blk  = blockIdx.x;
    const int kh   = tid >> 5;       // warp id = K-slice id
    const int lane = tid & 31;
    const unsigned smem_u32 = (unsigned)__cvta_generic_to_shared(smem);

    // one-time: stage Wh slice as fp16 B fragments (single plane)
    for (int idx = tid; idx < 32 * 1024; idx += 256) {
        int k = idx >> 5, n = idx & 31;
        int gcol = ((n >> 3) << 10) + (blk << 3) + (n & 7);
        float w = Wh[(size_t)k * GG + gcol];
        int kc = k & 15;
        int ln = ((n & 7) << 2) + ((kc & 7) >> 1);
        int by = (((n >> 3) & 1) << 3) + (((kc >> 3) & 1) << 2) + ((kc & 1) << 1);
        int base = WOFF + (((k >> 4) << 1) + (n >> 4)) * 512 + (ln << 4) + by;
        *(__half*)(smem + base) = __float2half_rn(w);
    }
    __syncthreads();

    const int ub = tid & 63;
    const int up = tid >> 6;       // 0..3; thread owns adjacent units 2up, 2up+1
    float creg[2] = {0.f, 0.f};

    // prefetch xp[0] into buffer 0
    {
#pragma unroll
        for (int e = 0; e < 2; e++) {
            int idx = tid * 2 + e;
            int b_ = idx >> 3, gate = (idx >> 1) & 3, half = idx & 1;
            const float* s = g_xp + (size_t)b_ * GG
                           + gate * HH + (blk << 3) + half * 4;
            unsigned d = smem_u32 + XPOFF
                       + (b_ * XP_STRIDE + gate * 8 + half * 4) * 4;
            cpasync16(d, s);
        }
        asm volatile("cp.async.commit_group;");
    }

    for (int t = 0; t < TT; t++) {
        const char* hsrc = (const char*)g_hstage[t & 1];

        // prefetch xp[t+1] into the other buffer
        if (t + 1 < TT) {
#pragma unroll
            for (int e = 0; e < 2; e++) {
                int idx = tid * 2 + e;
                int b_ = idx >> 3, gate = (idx >> 1) & 3, half = idx & 1;
                const float* s = g_xp + ((size_t)(t + 1) * BB + b_) * GG
                               + gate * HH + (blk << 3) + half * 4;
                unsigned d = smem_u32 + XPOFF + ((t + 1) & 1) * XPBUF
                           + (b_ * XP_STRIDE + gate * 8 + half * 4) * 4;
                cpasync16(d, s);
            }
        }
        asm volatile("cp.async.commit_group;");

        float acc[4][4][4];
#pragma unroll
        for (int i = 0; i < 4; i++)
#pragma unroll
            for (int j = 0; j < 4; j++)
#pragma unroll
                for (int q = 0; q < 4; q++) acc[i][j][q] = 0.f;

        // software-pipelined GEMM: prefetch chunk c+1's A while doing MMA(c)
        uint4 acur[4], anxt[4];
#pragma unroll
        for (int mt = 0; mt < 4; mt++) {
            size_t byteoff = (size_t)(kh * 4 + mt) * 512 + (lane << 4);
            acur[mt] = ldgcg128((const uint4*)(hsrc + byteoff));
        }
#pragma unroll
        for (int c = 0; c < 8; c++) {
            if (c < 7) {
#pragma unroll
                for (int mt = 0; mt < 4; mt++) {
                    size_t byteoff = (size_t)(c + 1) * ABUF_BYTES
                                   + (kh * 4 + mt) * 512 + (lane << 4);
                    anxt[mt] = ldgcg128((const uint4*)(hsrc + byteoff));
                }
            }
            const int ktg = c * 8 + kh;
            unsigned bb0 = smem_u32 + WOFF + (ktg * 2 + 0) * 512 + (lane << 4);
            unsigned bb1 = smem_u32 + WOFF + (ktg * 2 + 1) * 512 + (lane << 4);
            uint4 b0 = lds128(bb0);
            uint4 b1 = lds128(bb1);
#pragma unroll
            for (int mt = 0; mt < 4; mt++) {
                mma16816h(acc[mt][0], acur[mt], b0.x, b0.y);
                mma16816h(acc[mt][1], acur[mt], b0.z, b0.w);
                mma16816h(acc[mt][2], acur[mt], b1.x, b1.y);
                mma16816h(acc[mt][3], acur[mt], b1.z, b1.w);
            }
#pragma unroll
            for (int mt = 0; mt < 4; mt++) acur[mt] = anxt[mt];
        }

        // ---- write per-kh partial D (dedicated region, no aliasing) ----
        {
            float* P = (float*)(smem + POFF + kh * PART_RB);
            int g = lane >> 2, tq = lane & 3;
#pragma unroll
            for (int mt = 0; mt < 4; mt++) {
#pragma unroll
                for (int nj = 0; nj < 4; nj++) {
                    int row = mt * 16 + g;
                    int col = nj * 8 + tq * 2;
                    *(float2*)&P[row * PART_STRIDE + col] =
                        make_float2(acc[mt][nj][0], acc[mt][nj][1]);
                    *(float2*)&P[(row + 8) * PART_STRIDE + col] =
                        make_float2(acc[mt][nj][2], acc[mt][nj][3]);
                }
            }
        }
        asm volatile("cp.async.wait_group 1;");   // xp[t] ready (older group)
        __syncthreads();                          // partials visible block-wide

        // ---- pointwise LSTM update: adjacent units 2up, 2up+1 ----
        {
            const float* xps = (const float*)(smem + XPOFF + (t & 1) * XPBUF);
            char* hdst = (char*)g_hstage[(t + 1) & 1];
            float hn[2];
#pragma unroll
            for (int pi = 0; pi < 2; pi++) {
                int p = 2 * up + pi;
                float gv[4];
#pragma unroll
                for (int type = 0; type < 4; type++) {
                    int n = type * 8 + p;
                    float s = xps[ub * XP_STRIDE + n];
#pragma unroll
                    for (int r = 0; r < 8; r++)
                        s += ((const float*)(smem + POFF + r * PART_RB))[ub * PART_STRIDE + n];
                    gv[type] = s;
                }
                float si = 1.f / (1.f + expf(-gv[0]));
                float sf = 1.f / (1.f + expf(-gv[1]));
                float tg = tanhf(gv[2]);
                float so = 1.f / (1.f + expf(-gv[3]));
                float cn = fmaf(sf, creg[pi], si * tg);
                creg[pi] = cn;
                hn[pi] = so * tanhf(cn);
                if (t == TT - 1) g_h[ub * HH + (blk << 3) + p] = hn[pi];
            }

            // packed u32 store: units 2up (lo half) and 2up+1 (hi half)
            {
                int unit0 = (blk << 3) + 2 * up;      // even unit
                int r = ub & 15, mt = ub >> 4;
                int kc = unit0 & 15, ktile = unit0 >> 4;
                int ln  = ((r & 7) << 2) + ((kc & 7) >> 1);
                int reg = (((kc >> 3) & 1) << 1) + ((r >> 3) & 1);
                int off = (ktile * 4 + mt) * 512 + (ln << 4) + (reg << 2);
                unsigned h0 = (unsigned)__half_as_ushort(__float2half_rn(hn[0]));
                unsigned h1 = (unsigned)__half_as_ushort(__float2half_rn(hn[1]));
                *(unsigned*)(hdst + off) = h0 | (h1 << 16);
            }
        }

        // ---- release/acquire grid barrier (no per-thread membars) ----
        // __syncthreads orders all threads' h-stores before t0's release-add
        // (cumulativity); consumer side: t0 acquire-load + __syncthreads
        // orders the block's subsequent LDG.cg h-reads after producers' stores.
        __syncthreads();
        if (tid == 0) {
            asm volatile("red.release.gpu.global.add.u32 [%0], %1;"
                         :: "l"(&g_bar), "r"(1u) : "memory");
            unsigned tgt = (unsigned)(NBLK * (t + 1));
            unsigned v;
            while (true) {
                asm volatile("ld.acquire.gpu.global.u32 %0, [%1];"
                             : "=r"(v) : "l"(&g_bar) : "memory");
                if (v >= tgt) break;
                __nanosleep(32);
            }
        }
        __syncthreads();
    }
}

// ---------------------------------------------------------------------------
// classifier: 64 blocks (one per batch), 128 threads.
// ---------------------------------------------------------------------------
__global__ __launch_bounds__(128) void classifier_kernel(
        const float* __restrict__ Wd, const float* __restrict__ bd,
        float* __restrict__ out) {
    __shared__ float4 red[4];
    int b = blockIdx.x, tid = threadIdx.x;
    int lane = tid & 31, warp = tid >> 5;
    float4 a = make_float4(0.f, 0.f, 0.f, 0.f);
    for (int k = tid; k < HH; k += 128) {
        float h = g_h[b * HH + k];
        float4 w = *(const float4*)(Wd + k * CC);
        a.x = fmaf(h, w.x, a.x); a.y = fmaf(h, w.y, a.y);
        a.z = fmaf(h, w.z, a.z); a.w = fmaf(h, w.w, a.w);
    }
#pragma unroll
    for (int s = 16; s > 0; s >>= 1) {
        a.x += __shfl_xor_sync(0xffffffffu, a.x, s);
        a.y += __shfl_xor_sync(0xffffffffu, a.y, s);
        a.z += __shfl_xor_sync(0xffffffffu, a.z, s);
        a.w += __shfl_xor_sync(0xffffffffu, a.w, s);
    }
    if (lane == 0) red[warp] = a;
    __syncthreads();
    if (tid == 0) {
        float4 s = red[0];
        s.x += red[1].x + red[2].x + red[3].x;
        s.y += red[1].y + red[2].y + red[3].y;
        s.z += red[1].z + red[2].z + red[3].z;
        s.w += red[1].w + red[2].w + red[3].w;
        out[b * CC + 0] = s.x + bd[0];
        out[b * CC + 1] = s.y + bd[1];
        out[b * CC + 2] = s.z + bd[2];
        out[b * CC + 3] = s.w + bd[3];
    }
}

// ---------------------------------------------------------------------------
// launch: 6 graph nodes
// ---------------------------------------------------------------------------
extern "C" void kernel_launch(void* const* d_in, const int* in_sizes, int n_in,
                              void* d_out, int out_size) {
    const int*   tokens = (const int*)d_in[0];
    const float* emb    = (const float*)d_in[1];
    const float* Wi     = (const float*)d_in[2];
    const float* Wh     = (const float*)d_in[3];
    const float* bias   = (const float*)d_in[4];
    const float* Wd     = (const float*)d_in[5];
    const float* bd     = (const float*)d_in[6];
    float* out = (float*)d_out;

    cudaFuncSetAttribute(recurrence_kernel,
                         cudaFuncAttributeMaxDynamicSharedMemorySize, SMEM_BYTES);
    cudaFuncSetAttribute(xgemm_kernel,
                         cudaFuncAttributeMaxDynamicSharedMemorySize, XG_SMEM);

    init_kernel<<<64, 256>>>();
    conv_a_kernel<<<2048 * 32 / 8, 256>>>(tokens, emb);
    conv_b_kernel<<<32 * 256 / 8, 256>>>(Wi);

    dim3 xg(256, 32);
    xgemm_kernel<<<xg, 256, XG_SMEM>>>(bias);

    recurrence_kernel<<<NBLK, 256, SMEM_BYTES>>>(Wh);

    classifier_kernel<<<BB, 128>>>(Wd, bd, out);
}